// round 9
// baseline (speedup 1.0000x reference)
#include <cuda_runtime.h>

#define DIM 8192
typedef unsigned long long u64;

// XOR swizzle: conflict-free smem for all structured layouts used below.
__device__ __forceinline__ int phys(int i) {
    return i ^ ((i >> 4) & 15);
}

// Phase tables (shared by all batch rows):
//   g_t0[i] = layer-0 phi diagonal (applied to the real input)
//   g_t1a   = B0(i)*A1(M0(i)), rearranged for a coalesced gather in layout C'.
// All trailing diagonals are unit-modulus under |amp|^2 -> dropped.
__device__ float2 g_t0[DIM];
__device__ float2 g_t1a[DIM];

#define ROWS1_INIT {8191,8190,8188,8184,8176,8160,8128,8064,7936,7680,7168,6144,4095}

__global__ void qc_setup(const float* __restrict__ w) {
    const int i = blockIdx.x * blockDim.x + threadIdx.x;   // 0..8191
    const int ROWS1[13] = ROWS1_INIT;
    float a0 = 0.f, b0 = 0.f;
#pragma unroll
    for (int q = 0; q < 13; q++) {
        const float sgn = ((i >> (12 - q)) & 1) ? 0.5f : -0.5f;
        a0 += sgn * w[q*3 + 0];       // layer-0 phi
        b0 += sgn * w[q*3 + 2];       // layer-0 omega
    }
    int j = 0;
#pragma unroll
    for (int t = 0; t < 13; t++) j |= (__popc(ROWS1[t] & i) & 1) << t;
    float a1 = 0.f;
#pragma unroll
    for (int q = 0; q < 13; q++) {
        const float sgn = ((j >> (12 - q)) & 1) ? 0.5f : -0.5f;
        a1 += sgn * w[39 + q*3 + 0];  // layer-1 phi at M0-permuted index
    }
    float c, s;
    sincosf(a0, &s, &c);      g_t0[i] = make_float2(c, s);
    sincosf(b0 + a1, &s, &c); g_t1a[((i & 511) << 4) | (i >> 9)] = make_float2(c, s);
}

// Plain single-bit real RY rotation on register-bit BQ (scalar).
template<int BQ>
__device__ __forceinline__ void rotY(float (&re)[16], float (&im)[16],
                                     float c, float s) {
#pragma unroll
    for (int k0 = 0; k0 < 16; k0++) {
        if (k0 & (1 << BQ)) continue;
        const int k1 = k0 | (1 << BQ);
        const float r0 = re[k0], r1 = re[k1], i0 = im[k0], i1 = im[k1];
        re[k0] = fmaf(c, r0, -s * r1);
        re[k1] = fmaf(s, r0,  c * r1);
        im[k0] = fmaf(c, i0, -s * i1);
        im[k1] = fmaf(s, i0,  c * i1);
    }
}

__global__ void __launch_bounds__(512, 2)
qc_kernel(const float* __restrict__ x, const float* __restrict__ w,
          float* __restrict__ out)
{
    extern __shared__ float2 st[];                 // 8192 complex amps = 64 KB
    __shared__ float gc[26], gs[26];               // RY coeffs (scalar)
    __shared__ float red[16], red2[16];

    const int t    = threadIdx.x;
    const int b    = blockIdx.x;                   // one batch row per CTA
    const int lane = t & 31;
    const int warp = t >> 5;
    const int cbase = warp << 9;

    // Gate coefficients into smem (threads 0-25). The barrier making these
    // visible is BELOW, hidden under the global-load latency of x.
    if (t < 26) {
        const int l = t / 13, q = t - l * 13;
        float s, c; sincosf(0.5f * w[l*39 + q*3 + 1], &s, &c);
        gc[t] = c; gs[t] = s;
    }

    // ---- load row (layout A1: i = (t<<4)|k). Normalization deferred:
    // the circuit is linear; carry ss = ||x||^2, divide at the end.
    float re[16], im[16];
    const float4* xp = reinterpret_cast<const float4*>(x + (size_t)b * DIM + (t << 4));
    float ss = 0.f;
#pragma unroll
    for (int k4 = 0; k4 < 4; k4++) {
        const float4 v = xp[k4];
        re[k4*4+0] = v.x; re[k4*4+1] = v.y; re[k4*4+2] = v.z; re[k4*4+3] = v.w;
        ss = fmaf(v.x, v.x, fmaf(v.y, v.y, fmaf(v.z, v.z, fmaf(v.w, v.w, ss))));
    }

    __syncthreads();   // BAR 1: gate coeffs visible (hidden under x-load latency)

    // ---- A0: layer-0 phi phase on the (unnormalized) real input ----
    const float4* t0p = reinterpret_cast<const float4*>(g_t0) + (t << 3);
#pragma unroll
    for (int kk = 0; kk < 8; kk++) {
        const float4 cs = __ldg(&t0p[kk]);
        const int k0 = 2*kk, k1 = 2*kk + 1;
        const float x0 = re[k0];
        re[k0] = x0 * cs.x; im[k0] = x0 * cs.y;
        const float x1 = re[k1];
        re[k1] = x1 * cs.z; im[k1] = x1 * cs.w;
    }

    // ==== LAYER 0 ====
    // pass A1: reg bits = i bits 0-3 (qubits 12..9)
    rotY<0>(re, im, gc[12], gs[12]);
    rotY<1>(re, im, gc[11], gs[11]);
    rotY<2>(re, im, gc[10], gs[10]);
    rotY<3>(re, im, gc[ 9], gs[ 9]);

    // warp-local exchange A1 -> A2 (reg bits = i bits 4-7)
    const int a2base = cbase | ((lane & 16) << 4) | (lane & 15);
#pragma unroll
    for (int k = 0; k < 16; k++)
        st[phys(cbase | (lane << 4) | k)] = make_float2(re[k], im[k]);
    __syncwarp();
#pragma unroll
    for (int k = 0; k < 16; k++) {
        const float2 v = st[phys(a2base | (k << 4))];
        re[k] = v.x; im[k] = v.y;
    }
    rotY<0>(re, im, gc[8], gs[8]);
    rotY<1>(re, im, gc[7], gs[7]);
    rotY<2>(re, im, gc[6], gs[6]);
    rotY<3>(re, im, gc[5], gs[5]);
    // shfl gate on i bit 8 (= lane bit 4), qubit 4
    {
        const float cg = gc[4];
        const float sg = (lane & 16) ? gs[4] : -gs[4];
#pragma unroll
        for (int k = 0; k < 16; k++) {
            const float pr = __shfl_xor_sync(0xffffffffu, re[k], 16);
            const float pi = __shfl_xor_sync(0xffffffffu, im[k], 16);
            re[k] = fmaf(cg, re[k], sg * pr);
            im[k] = fmaf(cg, im[k], sg * pi);
        }
    }

    // block exchange A2 -> C' : i = (k<<9) | pt, pt = (lane<<4) | warp
#pragma unroll
    for (int k = 0; k < 16; k++)
        st[phys(a2base | (k << 4))] = make_float2(re[k], im[k]);
    __syncthreads();                                             // BAR 2
    const int pt = (lane << 4) | warp;
#pragma unroll
    for (int k = 0; k < 16; k++) {
        const float2 v = st[phys((k << 9) | pt)];
        re[k] = v.x; im[k] = v.y;
    }
    // pass C': reg bits = i bits 9-12 (qubits 3..0)
    rotY<0>(re, im, gc[3], gs[3]);
    rotY<1>(re, im, gc[2], gs[2]);
    rotY<2>(re, im, gc[1], gs[1]);
    rotY<3>(re, im, gc[0], gs[0]);

    // ==== D01 diagonal (layer-0 omega + layer-1 phi @ M0(i)) ====
    const float4* t1p = reinterpret_cast<const float4*>(g_t1a) + (pt << 3);
#pragma unroll
    for (int kk = 0; kk < 8; kk++) {
        const float4 cs = __ldg(&t1p[kk]);
        {
            const int k0 = 2*kk;
            const float tr = fmaf(cs.x, re[k0], -cs.y * im[k0]);
            const float ti = fmaf(cs.y, re[k0],  cs.x * im[k0]);
            re[k0] = tr; im[k0] = ti;
        }
        {
            const int k1 = 2*kk + 1;
            const float tr = fmaf(cs.z, re[k1], -cs.w * im[k1]);
            const float ti = fmaf(cs.w, re[k1],  cs.z * im[k1]);
            re[k1] = tr; im[k1] = ti;
        }
    }

    // ==== LAYER 1: the 4 observable-relevant gates, conjugated by M0 ====
    // d12 = {11,12} (k-mask 12), orient = parity(i & 4095) : gate 13 (qubit 0)
    {
        const int Pt = __popc(pt) & 1;
        const float c = gc[13];
#pragma unroll
        for (int k0 = 0; k0 < 8; k0++) {
            const int k1 = k0 ^ 12;
            const float sa = (Pt ^ (__popc(k0 & 7) & 1)) ? gs[13] : -gs[13];
            const float ar = re[k0], ai = im[k0], br = re[k1], bi = im[k1];
            re[k0] = fmaf(c, ar,  sa * br);
            im[k0] = fmaf(c, ai,  sa * bi);
            re[k1] = fmaf(c, br, -sa * ar);
            im[k1] = fmaf(c, bi, -sa * ai);
        }
    }
    // d10 = {9,10} (k-mask 3), orient = parity(k & 14) : gate 15 (qubit 2)
    {
        const float c = gc[15];
#pragma unroll
        for (int k0 = 0; k0 < 16; k0++) {
            if ((k0 & 3) > 1) continue;
            const int k1 = k0 ^ 3;
            const float sa = (__popc(k0 & 14) & 1) ? gs[15] : -gs[15];
            const float ar = re[k0], ai = im[k0], br = re[k1], bi = im[k1];
            re[k0] = fmaf(c, ar,  sa * br);
            im[k0] = fmaf(c, ai,  sa * bi);
            re[k1] = fmaf(c, br, -sa * ar);
            im[k1] = fmaf(c, bi, -sa * ai);
        }
    }
    // d8 = {7,8} (lane-mask 24, shfl), orient = lane bit4 ^ parity(k) : gate 17 (qubit 4)
    {
        const float c = gc[17];
        const float sE = ((lane >> 4) & 1) ? gs[17] : -gs[17];
#pragma unroll
        for (int k = 0; k < 16; k++) {
            const float pr = __shfl_xor_sync(0xffffffffu, re[k], 24);
            const float pi = __shfl_xor_sync(0xffffffffu, im[k], 24);
            const float sc = (__popc(k) & 1) ? -sE : sE;
            re[k] = fmaf(c, re[k], sc * pr);
            im[k] = fmaf(c, im[k], sc * pi);
        }
    }
    // d6 = {5,6} (lane-mask 6, shfl), orient = parity(lane&28) ^ parity(k) : gate 19 (qubit 6)
    {
        const float c = gc[19];
        const float sE = (__popc(lane & 28) & 1) ? gs[19] : -gs[19];
#pragma unroll
        for (int k = 0; k < 16; k++) {
            const float pr = __shfl_xor_sync(0xffffffffu, re[k], 6);
            const float pi = __shfl_xor_sync(0xffffffffu, im[k], 6);
            const float sc = (__popc(k) & 1) ? -sE : sE;
            re[k] = fmaf(c, re[k], sc * pr);
            im[k] = fmaf(c, im[k], sc * pi);
        }
    }

    // ==== measurement: sign = parity(i & 4927) in i-space ====
    // thread part: lane-mask 19 ^ warp parity; k part: k-mask 9
    const int sgt = (__popc(lane & 19) + __popc(warp)) & 1;
    float acc = 0.f;
#pragma unroll
    for (int k = 0; k < 16; k++) {
        const float p = fmaf(re[k], re[k], im[k] * im[k]);
        acc += (__popc(k & 9) & 1) ? -p : p;
    }
    if (sgt) acc = -acc;
    // joint reduction of the signed sum and ||x||^2
#pragma unroll
    for (int o = 16; o > 0; o >>= 1) {
        acc += __shfl_xor_sync(0xffffffffu, acc, o);
        ss  += __shfl_xor_sync(0xffffffffu, ss,  o);
    }
    if (lane == 0) { red[warp] = acc; red2[warp] = ss; }
    __syncthreads();                                             // BAR 3
    if (t == 0) {
        float ta = 0.f, ts = 0.f;
#pragma unroll
        for (int r = 0; r < 16; r++) { ta += red[r]; ts += red2[r]; }
        out[b] = ta / ts;
    }
}

extern "C" void kernel_launch(void* const* d_in, const int* in_sizes, int n_in,
                              void* d_out, int out_size)
{
    const float* x = (const float*)d_in[0];
    const float* w = (const float*)d_in[1];
    float* out = (float*)d_out;
    const int B = in_sizes[0] / DIM;               // one batch row per CTA

    qc_setup<<<DIM / 256, 256>>>(w);

    const size_t shmem = DIM * sizeof(float2);     // 64 KB
    cudaFuncSetAttribute(qc_kernel, cudaFuncAttributeMaxDynamicSharedMemorySize,
                         (int)shmem);
    qc_kernel<<<B, 512, shmem>>>(x, w, out);
}

// round 10
// speedup vs baseline: 1.1231x; 1.1231x over previous
#include <cuda_runtime.h>

#define DIM 8192
typedef unsigned long long u64;

// ---- packed f32x2 helpers (SASS FFMA2/FMUL2 path, PTX-only) ----
__device__ __forceinline__ float2 f2fma(float2 a, float2 b, float2 c) {
    u64 r, au = *(u64*)&a, bu = *(u64*)&b, cu = *(u64*)&c;
    asm("fma.rn.f32x2 %0,%1,%2,%3;" : "=l"(r) : "l"(au), "l"(bu), "l"(cu));
    return *(float2*)&r;
}
__device__ __forceinline__ float2 f2mul(float2 a, float2 b) {
    u64 r, au = *(u64*)&a, bu = *(u64*)&b;
    asm("mul.rn.f32x2 %0,%1,%2;" : "=l"(r) : "l"(au), "l"(bu));
    return *(float2*)&r;
}
__device__ __forceinline__ float2 f2add(float2 a, float2 b) {
    u64 r, au = *(u64*)&a, bu = *(u64*)&b;
    asm("add.rn.f32x2 %0,%1,%2;" : "=l"(r) : "l"(au), "l"(bu));
    return *(float2*)&r;
}

// XOR-linear swizzle: conflict-free for A1/A2/C'/L'' patterns (verified:
// each 8-lane phase's varying i-bits land on distinct phys bits 0-2).
__device__ __forceinline__ int phys(int i) {
    return i ^ ((i >> 4) & 15) ^ ((i >> 7) & 4) ^ ((i >> 9) & 2);
}

// Phase tables (shared by all batch rows):
//   g_t0[i] = layer-0 phi diagonal (applied to the real input)
//   g_t1a   = B0(i)*A1(M0(i)), rearranged for a coalesced gather in layout C'.
// All trailing diagonals are unit-modulus under |amp|^2 -> dropped.
__device__ float2 g_t0[DIM];
__device__ float2 g_t1a[DIM];

#define ROWS1_INIT {8191,8190,8188,8184,8176,8160,8128,8064,7936,7680,7168,6144,4095}

__global__ void qc_setup(const float* __restrict__ w) {
    const int i = blockIdx.x * blockDim.x + threadIdx.x;   // 0..8191
    const int ROWS1[13] = ROWS1_INIT;
    float a0 = 0.f, b0 = 0.f;
#pragma unroll
    for (int q = 0; q < 13; q++) {
        const float sgn = ((i >> (12 - q)) & 1) ? 0.5f : -0.5f;
        a0 += sgn * w[q*3 + 0];       // layer-0 phi
        b0 += sgn * w[q*3 + 2];       // layer-0 omega
    }
    int j = 0;
#pragma unroll
    for (int t = 0; t < 13; t++) j |= (__popc(ROWS1[t] & i) & 1) << t;
    float a1 = 0.f;
#pragma unroll
    for (int q = 0; q < 13; q++) {
        const float sgn = ((j >> (12 - q)) & 1) ? 0.5f : -0.5f;
        a1 += sgn * w[39 + q*3 + 0];  // layer-1 phi at M0-permuted index
    }
    float c, s;
    sincosf(a0, &s, &c);      g_t0[i] = make_float2(c, s);
    sincosf(b0 + a1, &s, &c); g_t1a[((i & 511) << 4) | (i >> 9)] = make_float2(c, s);
}

// Plain single-bit real RY rotation on register-bit BQ (packed).
template<int BQ>
__device__ __forceinline__ void rotY(float2 (&re)[16], float2 (&im)[16],
                                     float2 c, float2 s, float2 ns) {
#pragma unroll
    for (int k0 = 0; k0 < 16; k0++) {
        if (k0 & (1 << BQ)) continue;
        const int k1 = k0 | (1 << BQ);
        const float2 r0 = re[k0], r1 = re[k1], i0 = im[k0], i1 = im[k1];
        re[k0] = f2fma(c, r0, f2mul(ns, r1));
        re[k1] = f2fma(s, r0, f2mul(c,  r1));
        im[k0] = f2fma(c, i0, f2mul(ns, i1));
        im[k1] = f2fma(s, i0, f2mul(c,  i1));
    }
}

__global__ void __launch_bounds__(512, 1)
qc_kernel(const float* __restrict__ x, const float* __restrict__ w,
          float* __restrict__ out)
{
    extern __shared__ float4 st[];                 // 8192 x (re-pack, im-pack) = 128 KB
    __shared__ float2 gc[26], gs[26], gns[26];     // RY coeffs, duplicated packed
    __shared__ float2 red[16], red2[16];

    const int t    = threadIdx.x;
    const int b    = blockIdx.x;                   // batch rows 2b, 2b+1
    const int lane = t & 31;
    const int warp = t >> 5;
    const int cbase = warp << 9;

    // Gate coefficients into smem (threads 0-25). Barrier below, hidden
    // under the global-load latency of x.
    if (t < 26) {
        const int l = t / 13, q = t - l * 13;
        float s, c; sincosf(0.5f * w[l*39 + q*3 + 1], &s, &c);
        gc[t]  = make_float2( c,  c);
        gs[t]  = make_float2( s,  s);
        gns[t] = make_float2(-s, -s);
    }

    // ---- load two rows (layout A1: i = (t<<4)|k). Normalization deferred:
    // the circuit is linear; carry ss = ||x||^2, divide at the end.
    float2 re[16], im[16];
    const float4* xp0 = reinterpret_cast<const float4*>(x + (size_t)(2*b)   * DIM + (t << 4));
    const float4* xp1 = reinterpret_cast<const float4*>(x + (size_t)(2*b+1) * DIM + (t << 4));
    float2 ss = make_float2(0.f, 0.f);
#pragma unroll
    for (int k4 = 0; k4 < 4; k4++) {
        const float4 v0 = xp0[k4];
        const float4 v1 = xp1[k4];
        re[k4*4+0] = make_float2(v0.x, v1.x);
        re[k4*4+1] = make_float2(v0.y, v1.y);
        re[k4*4+2] = make_float2(v0.z, v1.z);
        re[k4*4+3] = make_float2(v0.w, v1.w);
    }
#pragma unroll
    for (int k = 0; k < 16; k++) ss = f2fma(re[k], re[k], ss);

    __syncthreads();   // BAR 1: gate coeffs visible (hidden under x-load latency)

    // ---- A0: layer-0 phi phase on the (unnormalized) real input ----
    const float4* t0p = reinterpret_cast<const float4*>(g_t0) + (t << 3);
#pragma unroll
    for (int kk = 0; kk < 8; kk++) {
        const float4 cs = __ldg(&t0p[kk]);
        const int k0 = 2*kk, k1 = 2*kk + 1;
        const float2 x0 = re[k0];
        re[k0] = f2mul(x0, make_float2(cs.x, cs.x));
        im[k0] = f2mul(x0, make_float2(cs.y, cs.y));
        const float2 x1 = re[k1];
        re[k1] = f2mul(x1, make_float2(cs.z, cs.z));
        im[k1] = f2mul(x1, make_float2(cs.w, cs.w));
    }

    // ==== LAYER 0 ====
    // pass A1: reg bits = i bits 0-3 (qubits 12..9)
    rotY<0>(re, im, gc[12], gs[12], gns[12]);
    rotY<1>(re, im, gc[11], gs[11], gns[11]);
    rotY<2>(re, im, gc[10], gs[10], gns[10]);
    rotY<3>(re, im, gc[ 9], gs[ 9], gns[ 9]);

    // warp-local exchange A1 -> A2 (reg bits = i bits 4-7)
    const int a2base = cbase | ((lane & 16) << 4) | (lane & 15);
#pragma unroll
    for (int k = 0; k < 16; k++)
        st[phys(cbase | (lane << 4) | k)] = make_float4(re[k].x, re[k].y, im[k].x, im[k].y);
    __syncwarp();
#pragma unroll
    for (int k = 0; k < 16; k++) {
        const float4 v = st[phys(a2base | (k << 4))];
        re[k] = make_float2(v.x, v.y); im[k] = make_float2(v.z, v.w);
    }
    rotY<0>(re, im, gc[8], gs[8], gns[8]);
    rotY<1>(re, im, gc[7], gs[7], gns[7]);
    rotY<2>(re, im, gc[6], gs[6], gns[6]);
    rotY<3>(re, im, gc[5], gs[5], gns[5]);
    // shfl gate on i bit 8 (= lane bit 4), qubit 4
    {
        const float2 cg   = gc[4];
        const float2 sSel = (lane & 16) ? gs[4] : gns[4];
#pragma unroll
        for (int k = 0; k < 16; k++) {
            const u64 pr = __shfl_xor_sync(0xffffffffu, *(u64*)&re[k], 16);
            const u64 pi = __shfl_xor_sync(0xffffffffu, *(u64*)&im[k], 16);
            re[k] = f2fma(cg, re[k], f2mul(sSel, *(const float2*)&pr));
            im[k] = f2fma(cg, im[k], f2mul(sSel, *(const float2*)&pi));
        }
    }

    // block exchange A2 -> C' : i = (k<<9) | pt, pt = (lane<<4) | warp
#pragma unroll
    for (int k = 0; k < 16; k++)
        st[phys(a2base | (k << 4))] = make_float4(re[k].x, re[k].y, im[k].x, im[k].y);
    __syncthreads();                                             // BAR 2
    const int pt = (lane << 4) | warp;
#pragma unroll
    for (int k = 0; k < 16; k++) {
        const float4 v = st[phys((k << 9) | pt)];
        re[k] = make_float2(v.x, v.y); im[k] = make_float2(v.z, v.w);
    }
    // pass C': reg bits = i bits 9-12 (qubits 3..0)
    rotY<0>(re, im, gc[3], gs[3], gns[3]);
    rotY<1>(re, im, gc[2], gs[2], gns[2]);
    rotY<2>(re, im, gc[1], gs[1], gns[1]);
    rotY<3>(re, im, gc[0], gs[0], gns[0]);

    // ==== D01 diagonal (layer-0 omega + layer-1 phi @ M0(i)) ====
    const float4* t1p = reinterpret_cast<const float4*>(g_t1a) + (pt << 3);
#pragma unroll
    for (int kk = 0; kk < 8; kk++) {
        const float4 cs = __ldg(&t1p[kk]);
        {
            const int k0 = 2*kk;
            const float2 cd = make_float2(cs.x, cs.x);
            const float2 sd = make_float2(cs.y, cs.y);
            const float2 nd = make_float2(-cs.y, -cs.y);
            const float2 tr = f2fma(cd, re[k0], f2mul(nd, im[k0]));
            const float2 ti = f2fma(sd, re[k0], f2mul(cd, im[k0]));
            re[k0] = tr; im[k0] = ti;
        }
        {
            const int k1 = 2*kk + 1;
            const float2 cd = make_float2(cs.z, cs.z);
            const float2 sd = make_float2(cs.w, cs.w);
            const float2 nd = make_float2(-cs.w, -cs.w);
            const float2 tr = f2fma(cd, re[k1], f2mul(nd, im[k1]));
            const float2 ti = f2fma(sd, re[k1], f2mul(cd, im[k1]));
            re[k1] = tr; im[k1] = ti;
        }
    }

    // ==== LAYER 1: 4 observable-relevant gates, conjugated by M0 ====
    // d12 = {11,12} (k-mask 12), orient = parity(i & 4095) : gate 13 (qubit 0)
    {
        const int Pt = __popc(pt) & 1;
        const float2 c = gc[13];
#pragma unroll
        for (int k0 = 0; k0 < 8; k0++) {
            const int k1 = k0 ^ 12;
            const int o = Pt ^ (__popc(k0 & 7) & 1);
            const float2 sa = o ? gs[13] : gns[13];
            const float2 sb = o ? gns[13] : gs[13];
            const float2 ar = re[k0], ai = im[k0], br = re[k1], bi = im[k1];
            re[k0] = f2fma(c, ar, f2mul(sa, br));
            im[k0] = f2fma(c, ai, f2mul(sa, bi));
            re[k1] = f2fma(c, br, f2mul(sb, ar));
            im[k1] = f2fma(c, bi, f2mul(sb, ai));
        }
    }
    // d10 = {9,10} (k-mask 3), orient = parity(k & 14) : gate 15 (qubit 2)
    {
        const float2 c = gc[15];
#pragma unroll
        for (int k0 = 0; k0 < 16; k0++) {
            if ((k0 & 3) > 1) continue;
            const int k1 = k0 ^ 3;
            const int o = __popc(k0 & 14) & 1;
            const float2 sa = o ? gs[15] : gns[15];
            const float2 sb = o ? gns[15] : gs[15];
            const float2 ar = re[k0], ai = im[k0], br = re[k1], bi = im[k1];
            re[k0] = f2fma(c, ar, f2mul(sa, br));
            im[k0] = f2fma(c, ai, f2mul(sa, bi));
            re[k1] = f2fma(c, br, f2mul(sb, ar));
            im[k1] = f2fma(c, bi, f2mul(sb, ai));
        }
    }

    // ==== warp-local exchange C' -> L'' (slots with i bits 0-3 = warp are
    // warp-private in both layouts; syncwarp suffices) ====
    // L'': regs k = i bits 5-8; lane bit0 = i bit 4, lane bits 1-4 = i bits 9-12
#pragma unroll
    for (int k = 0; k < 16; k++)
        st[phys((k << 9) | pt)] = make_float4(re[k].x, re[k].y, im[k].x, im[k].y);
    __syncwarp();
    const int lbase = ((lane >> 1) << 9) | ((lane & 1) << 4) | warp;
#pragma unroll
    for (int k = 0; k < 16; k++) {
        const float4 v = st[phys(lbase | (k << 5))];
        re[k] = make_float2(v.x, v.y); im[k] = make_float2(v.z, v.w);
    }

    // d8 = {7,8} (k-mask 12 in L''), orient = k bit3 ^ parity(i bits 9-12 = lane&30)
    {
        const float2 c = gc[17];
        const int oL = __popc(lane & 30) & 1;
        const float2 sa = oL ? gs[17] : gns[17];   // o(k0)=oL since k0 bit3=0
        const float2 sb = oL ? gns[17] : gs[17];
#pragma unroll
        for (int k0 = 0; k0 < 8; k0++) {
            const int k1 = k0 ^ 12;
            const float2 ar = re[k0], ai = im[k0], br = re[k1], bi = im[k1];
            re[k0] = f2fma(c, ar, f2mul(sa, br));
            im[k0] = f2fma(c, ai, f2mul(sa, bi));
            re[k1] = f2fma(c, br, f2mul(sb, ar));
            im[k1] = f2fma(c, bi, f2mul(sb, ai));
        }
    }
    // d6 = {5,6} (k-mask 3 in L''), orient = parity(k&14) ^ parity(lane&30)
    {
        const float2 c = gc[19];
        const int oL = __popc(lane & 30) & 1;
#pragma unroll
        for (int k0 = 0; k0 < 16; k0++) {
            if ((k0 & 3) > 1) continue;
            const int k1 = k0 ^ 3;
            const int o = oL ^ (__popc(k0 & 14) & 1);
            const float2 sa = o ? gs[19] : gns[19];
            const float2 sb = o ? gns[19] : gs[19];
            const float2 ar = re[k0], ai = im[k0], br = re[k1], bi = im[k1];
            re[k0] = f2fma(c, ar, f2mul(sa, br));
            im[k0] = f2fma(c, ai, f2mul(sa, bi));
            re[k1] = f2fma(c, br, f2mul(sb, ar));
            im[k1] = f2fma(c, bi, f2mul(sb, ai));
        }
    }

    // ==== measurement: sign = parity(i & 4927), mask bits {0-5,8,9,12} ====
    // L'': warp = i bits 0-3 -> popc(warp); lane bits {0(i4),1(i9),4(i12)} -> 19;
    //      k bits {0(i5),3(i8)} -> 9
    const float2 mn1 = make_float2(-1.f, -1.f);
    const int sgt = (__popc(lane & 19) + __popc(warp)) & 1;
    float2 acc = make_float2(0.f, 0.f);
#pragma unroll
    for (int k = 0; k < 16; k++) {
        const float2 p = f2fma(re[k], re[k], f2mul(im[k], im[k]));
        if (__popc(k & 9) & 1) acc = f2fma(p, mn1, acc);
        else                   acc = f2add(acc, p);
    }
    if (sgt) acc = f2mul(acc, mn1);
    // joint reduction of the signed sum and ||x||^2
#pragma unroll
    for (int o = 16; o > 0; o >>= 1) {
        u64 av = *(u64*)&acc;
        u64 ov = __shfl_xor_sync(0xffffffffu, av, o);
        acc = f2add(acc, *(float2*)&ov);
        u64 sv = *(u64*)&ss;
        u64 so = __shfl_xor_sync(0xffffffffu, sv, o);
        ss = f2add(ss, *(float2*)&so);
    }
    if (lane == 0) { red[warp] = acc; red2[warp] = ss; }
    __syncthreads();                                             // BAR 3
    if (t == 0) {
        float2 ta = make_float2(0.f, 0.f);
        float2 ts = make_float2(0.f, 0.f);
#pragma unroll
        for (int r = 0; r < 16; r++) { ta = f2add(ta, red[r]); ts = f2add(ts, red2[r]); }
        out[2*b]   = ta.x / ts.x;
        out[2*b+1] = ta.y / ts.y;
    }
}

extern "C" void kernel_launch(void* const* d_in, const int* in_sizes, int n_in,
                              void* d_out, int out_size)
{
    const float* x = (const float*)d_in[0];
    const float* w = (const float*)d_in[1];
    float* out = (float*)d_out;
    const int B2 = (in_sizes[0] / DIM) / 2;        // 2 batch rows per CTA

    qc_setup<<<DIM / 256, 256>>>(w);

    const size_t shmem = DIM * sizeof(float4);     // 128 KB
    cudaFuncSetAttribute(qc_kernel, cudaFuncAttributeMaxDynamicSharedMemorySize,
                         (int)shmem);
    qc_kernel<<<B2, 512, shmem>>>(x, w, out);
}

// round 11
// speedup vs baseline: 1.1979x; 1.0667x over previous
#include <cuda_runtime.h>

#define DIM 8192
typedef unsigned long long u64;

// ---- packed f32x2 helpers (SASS FFMA2/FMUL2 path, PTX-only) ----
__device__ __forceinline__ float2 f2fma(float2 a, float2 b, float2 c) {
    u64 r, au = *(u64*)&a, bu = *(u64*)&b, cu = *(u64*)&c;
    asm("fma.rn.f32x2 %0,%1,%2,%3;" : "=l"(r) : "l"(au), "l"(bu), "l"(cu));
    return *(float2*)&r;
}
__device__ __forceinline__ float2 f2mul(float2 a, float2 b) {
    u64 r, au = *(u64*)&a, bu = *(u64*)&b;
    asm("mul.rn.f32x2 %0,%1,%2;" : "=l"(r) : "l"(au), "l"(bu));
    return *(float2*)&r;
}
__device__ __forceinline__ float2 f2add(float2 a, float2 b) {
    u64 r, au = *(u64*)&a, bu = *(u64*)&b;
    asm("add.rn.f32x2 %0,%1,%2;" : "=l"(r) : "l"(au), "l"(bu));
    return *(float2*)&r;
}

// XOR swizzle: conflict-free smem for all structured layouts used below.
__device__ __forceinline__ int phys(int i) {
    return i ^ ((i >> 4) & 15);
}

// Phase tables (shared by all batch rows):
//   g_t0[i] = layer-0 phi diagonal (applied to the real input)
//   g_t1a   = B0(i)*A1(M0(i)), rearranged for a coalesced gather in layout C'.
// All trailing diagonals are unit-modulus under |amp|^2 -> dropped.
__device__ float2 g_t0[DIM];
__device__ float2 g_t1a[DIM];

#define ROWS1_INIT {8191,8190,8188,8184,8176,8160,8128,8064,7936,7680,7168,6144,4095}

__global__ void qc_setup(const float* __restrict__ w) {
    const int i = blockIdx.x * blockDim.x + threadIdx.x;   // 0..8191
    const int ROWS1[13] = ROWS1_INIT;
    float a0 = 0.f, b0 = 0.f;
#pragma unroll
    for (int q = 0; q < 13; q++) {
        const float sgn = ((i >> (12 - q)) & 1) ? 0.5f : -0.5f;
        a0 += sgn * w[q*3 + 0];       // layer-0 phi
        b0 += sgn * w[q*3 + 2];       // layer-0 omega
    }
    int j = 0;
#pragma unroll
    for (int t = 0; t < 13; t++) j |= (__popc(ROWS1[t] & i) & 1) << t;
    float a1 = 0.f;
#pragma unroll
    for (int q = 0; q < 13; q++) {
        const float sgn = ((j >> (12 - q)) & 1) ? 0.5f : -0.5f;
        a1 += sgn * w[39 + q*3 + 0];  // layer-1 phi at M0-permuted index
    }
    float c, s;
    sincosf(a0, &s, &c);      g_t0[i] = make_float2(c, s);
    sincosf(b0 + a1, &s, &c); g_t1a[((i & 511) << 4) | (i >> 9)] = make_float2(c, s);
}

// Plain single-bit real RY rotation on register-bit BQ (packed).
template<int BQ>
__device__ __forceinline__ void rotY(float2 (&re)[16], float2 (&im)[16],
                                     float2 c, float2 s, float2 ns) {
#pragma unroll
    for (int k0 = 0; k0 < 16; k0++) {
        if (k0 & (1 << BQ)) continue;
        const int k1 = k0 | (1 << BQ);
        const float2 r0 = re[k0], r1 = re[k1], i0 = im[k0], i1 = im[k1];
        re[k0] = f2fma(c, r0, f2mul(ns, r1));
        re[k1] = f2fma(s, r0, f2mul(c,  r1));
        im[k0] = f2fma(c, i0, f2mul(ns, i1));
        im[k1] = f2fma(s, i0, f2mul(c,  i1));
    }
}

__global__ void __launch_bounds__(512, 1)
qc_kernel(const float* __restrict__ x, const float* __restrict__ w,
          float* __restrict__ out)
{
    extern __shared__ float4 st[];                 // 8192 x (re-pack, im-pack) = 128 KB
    __shared__ float2 gc[26], gs[26], gns[26];     // RY coeffs, duplicated packed
    __shared__ float2 red[16], red2[16];

    const int t    = threadIdx.x;
    const int b    = blockIdx.x;                   // batch rows 2b, 2b+1
    const int lane = t & 31;
    const int warp = t >> 5;
    const int cbase = warp << 9;

    // Gate coefficients into smem (threads 0-25). Barrier below, hidden
    // under the global-load latency of x.
    if (t < 26) {
        const int l = t / 13, q = t - l * 13;
        float s, c; sincosf(0.5f * w[l*39 + q*3 + 1], &s, &c);
        gc[t]  = make_float2( c,  c);
        gs[t]  = make_float2( s,  s);
        gns[t] = make_float2(-s, -s);
    }

    // ---- load two rows (layout A1: i = (t<<4)|k). Normalization deferred:
    // the circuit is linear; carry ss = ||x||^2, divide at the end.
    float2 re[16], im[16];
    const float4* xp0 = reinterpret_cast<const float4*>(x + (size_t)(2*b)   * DIM + (t << 4));
    const float4* xp1 = reinterpret_cast<const float4*>(x + (size_t)(2*b+1) * DIM + (t << 4));
    float2 ss = make_float2(0.f, 0.f);
#pragma unroll
    for (int k4 = 0; k4 < 4; k4++) {
        const float4 v0 = xp0[k4];
        const float4 v1 = xp1[k4];
        re[k4*4+0] = make_float2(v0.x, v1.x);
        re[k4*4+1] = make_float2(v0.y, v1.y);
        re[k4*4+2] = make_float2(v0.z, v1.z);
        re[k4*4+3] = make_float2(v0.w, v1.w);
    }
#pragma unroll
    for (int k = 0; k < 16; k++) ss = f2fma(re[k], re[k], ss);

    __syncthreads();   // BAR 1: gate coeffs visible (hidden under x-load latency)

    // ---- A0: layer-0 phi phase on the (unnormalized) real input ----
    const float4* t0p = reinterpret_cast<const float4*>(g_t0) + (t << 3);
#pragma unroll
    for (int kk = 0; kk < 8; kk++) {
        const float4 cs = __ldg(&t0p[kk]);
        const int k0 = 2*kk, k1 = 2*kk + 1;
        const float2 x0 = re[k0];
        re[k0] = f2mul(x0, make_float2(cs.x, cs.x));
        im[k0] = f2mul(x0, make_float2(cs.y, cs.y));
        const float2 x1 = re[k1];
        re[k1] = f2mul(x1, make_float2(cs.z, cs.z));
        im[k1] = f2mul(x1, make_float2(cs.w, cs.w));
    }

    // ==== LAYER 0 ====
    // pass A1: reg bits = i bits 0-3 (qubits 12..9)
    rotY<0>(re, im, gc[12], gs[12], gns[12]);
    rotY<1>(re, im, gc[11], gs[11], gns[11]);
    rotY<2>(re, im, gc[10], gs[10], gns[10]);
    rotY<3>(re, im, gc[ 9], gs[ 9], gns[ 9]);

    // warp-local exchange A1 -> A2 (reg bits = i bits 4-7)
    const int a2base = cbase | ((lane & 16) << 4) | (lane & 15);
#pragma unroll
    for (int k = 0; k < 16; k++)
        st[phys(cbase | (lane << 4) | k)] = make_float4(re[k].x, re[k].y, im[k].x, im[k].y);
    __syncwarp();
#pragma unroll
    for (int k = 0; k < 16; k++) {
        const float4 v = st[phys(a2base | (k << 4))];
        re[k] = make_float2(v.x, v.y); im[k] = make_float2(v.z, v.w);
    }
    rotY<0>(re, im, gc[8], gs[8], gns[8]);
    rotY<1>(re, im, gc[7], gs[7], gns[7]);
    rotY<2>(re, im, gc[6], gs[6], gns[6]);
    rotY<3>(re, im, gc[5], gs[5], gns[5]);
    // shfl gate on i bit 8 (= lane bit 4), qubit 4
    {
        const float2 cg   = gc[4];
        const float2 sSel = (lane & 16) ? gs[4] : gns[4];
#pragma unroll
        for (int k = 0; k < 16; k++) {
            const u64 pr = __shfl_xor_sync(0xffffffffu, *(u64*)&re[k], 16);
            const u64 pi = __shfl_xor_sync(0xffffffffu, *(u64*)&im[k], 16);
            re[k] = f2fma(cg, re[k], f2mul(sSel, *(const float2*)&pr));
            im[k] = f2fma(cg, im[k], f2mul(sSel, *(const float2*)&pi));
        }
    }

    // block exchange A2 -> C' : i = (k<<9) | pt, pt = (lane<<4) | warp
#pragma unroll
    for (int k = 0; k < 16; k++)
        st[phys(a2base | (k << 4))] = make_float4(re[k].x, re[k].y, im[k].x, im[k].y);
    __syncthreads();                                             // BAR 2
    const int pt = (lane << 4) | warp;
#pragma unroll
    for (int k = 0; k < 16; k++) {
        const float4 v = st[phys((k << 9) | pt)];
        re[k] = make_float2(v.x, v.y); im[k] = make_float2(v.z, v.w);
    }

    // Prefetch first half of the D01 phase table (covers LDG latency under
    // the C' gate pass below).
    const float4* t1p = reinterpret_cast<const float4*>(g_t1a) + (pt << 3);
    float4 tq0 = __ldg(&t1p[0]);
    float4 tq1 = __ldg(&t1p[1]);
    float4 tq2 = __ldg(&t1p[2]);
    float4 tq3 = __ldg(&t1p[3]);

    // pass C': reg bits = i bits 9-12 (qubits 3..0)
    rotY<0>(re, im, gc[3], gs[3], gns[3]);
    rotY<1>(re, im, gc[2], gs[2], gns[2]);
    rotY<2>(re, im, gc[1], gs[1], gns[1]);
    rotY<3>(re, im, gc[0], gs[0], gns[0]);

    // ==== D01 diagonal (layer-0 omega + layer-1 phi @ M0(i)) ====
#pragma unroll
    for (int kk = 0; kk < 8; kk++) {
        float4 cs;
        if      (kk == 0) cs = tq0;
        else if (kk == 1) cs = tq1;
        else if (kk == 2) cs = tq2;
        else if (kk == 3) cs = tq3;
        else              cs = __ldg(&t1p[kk]);
        {
            const int k0 = 2*kk;
            const float2 cd = make_float2(cs.x, cs.x);
            const float2 sd = make_float2(cs.y, cs.y);
            const float2 nd = make_float2(-cs.y, -cs.y);
            const float2 tr = f2fma(cd, re[k0], f2mul(nd, im[k0]));
            const float2 ti = f2fma(sd, re[k0], f2mul(cd, im[k0]));
            re[k0] = tr; im[k0] = ti;
        }
        {
            const int k1 = 2*kk + 1;
            const float2 cd = make_float2(cs.z, cs.z);
            const float2 sd = make_float2(cs.w, cs.w);
            const float2 nd = make_float2(-cs.w, -cs.w);
            const float2 tr = f2fma(cd, re[k1], f2mul(nd, im[k1]));
            const float2 ti = f2fma(sd, re[k1], f2mul(cd, im[k1]));
            re[k1] = tr; im[k1] = ti;
        }
    }

    // ==== LAYER 1: the 4 observable-relevant gates, conjugated by M0 ====
    // d12 = {11,12} (k-mask 12), orient = parity(i & 4095) : gate 13 (qubit 0)
    {
        const int Pt = __popc(pt) & 1;
        const float2 c = gc[13];
#pragma unroll
        for (int k0 = 0; k0 < 8; k0++) {
            const int k1 = k0 ^ 12;
            const int o = Pt ^ (__popc(k0 & 7) & 1);
            const float2 sa = o ? gs[13] : gns[13];
            const float2 sb = o ? gns[13] : gs[13];
            const float2 ar = re[k0], ai = im[k0], br = re[k1], bi = im[k1];
            re[k0] = f2fma(c, ar, f2mul(sa, br));
            im[k0] = f2fma(c, ai, f2mul(sa, bi));
            re[k1] = f2fma(c, br, f2mul(sb, ar));
            im[k1] = f2fma(c, bi, f2mul(sb, ai));
        }
    }
    // d10 = {9,10} (k-mask 3), orient = parity(k & 14) : gate 15 (qubit 2)
    {
        const float2 c = gc[15];
#pragma unroll
        for (int k0 = 0; k0 < 16; k0++) {
            if ((k0 & 3) > 1) continue;
            const int k1 = k0 ^ 3;
            const int o = __popc(k0 & 14) & 1;
            const float2 sa = o ? gs[15] : gns[15];
            const float2 sb = o ? gns[15] : gs[15];
            const float2 ar = re[k0], ai = im[k0], br = re[k1], bi = im[k1];
            re[k0] = f2fma(c, ar, f2mul(sa, br));
            im[k0] = f2fma(c, ai, f2mul(sa, bi));
            re[k1] = f2fma(c, br, f2mul(sb, ar));
            im[k1] = f2fma(c, bi, f2mul(sb, ai));
        }
    }
    // d8 = {7,8} (lane-mask 24, shfl), orient = lane bit4 ^ parity(k) : gate 17 (qubit 4)
    {
        const float2 c = gc[17];
        const int oL = (lane >> 4) & 1;
        const float2 sEv = oL ? gs[17] : gns[17];
        const float2 sOd = oL ? gns[17] : gs[17];
#pragma unroll
        for (int k = 0; k < 16; k++) {
            const u64 pr = __shfl_xor_sync(0xffffffffu, *(u64*)&re[k], 24);
            const u64 pi = __shfl_xor_sync(0xffffffffu, *(u64*)&im[k], 24);
            const float2 sc = (__popc(k) & 1) ? sOd : sEv;
            re[k] = f2fma(c, re[k], f2mul(sc, *(const float2*)&pr));
            im[k] = f2fma(c, im[k], f2mul(sc, *(const float2*)&pi));
        }
    }
    // d6 = {5,6} (lane-mask 6, shfl), orient = parity(lane&28) ^ parity(k) : gate 19 (qubit 6)
    {
        const float2 c = gc[19];
        const int oL = __popc(lane & 28) & 1;
        const float2 sEv = oL ? gs[19] : gns[19];
        const float2 sOd = oL ? gns[19] : gs[19];
#pragma unroll
        for (int k = 0; k < 16; k++) {
            const u64 pr = __shfl_xor_sync(0xffffffffu, *(u64*)&re[k], 6);
            const u64 pi = __shfl_xor_sync(0xffffffffu, *(u64*)&im[k], 6);
            const float2 sc = (__popc(k) & 1) ? sOd : sEv;
            re[k] = f2fma(c, re[k], f2mul(sc, *(const float2*)&pr));
            im[k] = f2fma(c, im[k], f2mul(sc, *(const float2*)&pi));
        }
    }

    // ==== measurement: sign = parity(i & 4927) in i-space ====
    // thread part: lane-mask 19 ^ warp parity; k part: k-mask 9
    const float2 mn1 = make_float2(-1.f, -1.f);
    const int sgt = (__popc(lane & 19) + __popc(warp)) & 1;
    float2 acc = make_float2(0.f, 0.f);
#pragma unroll
    for (int k = 0; k < 16; k++) {
        const float2 p = f2fma(re[k], re[k], f2mul(im[k], im[k]));
        if (__popc(k & 9) & 1) acc = f2fma(p, mn1, acc);
        else                   acc = f2add(acc, p);
    }
    if (sgt) acc = f2mul(acc, mn1);
    // joint reduction of the signed sum and ||x||^2
#pragma unroll
    for (int o = 16; o > 0; o >>= 1) {
        u64 av = *(u64*)&acc;
        u64 ov = __shfl_xor_sync(0xffffffffu, av, o);
        acc = f2add(acc, *(float2*)&ov);
        u64 sv = *(u64*)&ss;
        u64 so = __shfl_xor_sync(0xffffffffu, sv, o);
        ss = f2add(ss, *(float2*)&so);
    }
    if (lane == 0) { red[warp] = acc; red2[warp] = ss; }
    __syncthreads();                                             // BAR 3
    if (t == 0) {
        float2 ta = make_float2(0.f, 0.f);
        float2 ts = make_float2(0.f, 0.f);
#pragma unroll
        for (int r = 0; r < 16; r++) { ta = f2add(ta, red[r]); ts = f2add(ts, red2[r]); }
        out[2*b]   = ta.x / ts.x;
        out[2*b+1] = ta.y / ts.y;
    }
}

extern "C" void kernel_launch(void* const* d_in, const int* in_sizes, int n_in,
                              void* d_out, int out_size)
{
    const float* x = (const float*)d_in[0];
    const float* w = (const float*)d_in[1];
    float* out = (float*)d_out;
    const int B2 = (in_sizes[0] / DIM) / 2;        // 2 batch rows per CTA

    qc_setup<<<DIM / 256, 256>>>(w);

    const size_t shmem = DIM * sizeof(float4);     // 128 KB
    cudaFuncSetAttribute(qc_kernel, cudaFuncAttributeMaxDynamicSharedMemorySize,
                         (int)shmem);
    qc_kernel<<<B2, 512, shmem>>>(x, w, out);
}

// round 12
// speedup vs baseline: 1.4747x; 1.2311x over previous
#include <cuda_runtime.h>

#define DIM 8192
typedef unsigned long long u64;

// ---- packed f32x2 helpers (SASS FFMA2/FMUL2 path, PTX-only) ----
__device__ __forceinline__ float2 f2fma(float2 a, float2 b, float2 c) {
    u64 r, au = *(u64*)&a, bu = *(u64*)&b, cu = *(u64*)&c;
    asm("fma.rn.f32x2 %0,%1,%2,%3;" : "=l"(r) : "l"(au), "l"(bu), "l"(cu));
    return *(float2*)&r;
}
__device__ __forceinline__ float2 f2mul(float2 a, float2 b) {
    u64 r, au = *(u64*)&a, bu = *(u64*)&b;
    asm("mul.rn.f32x2 %0,%1,%2;" : "=l"(r) : "l"(au), "l"(bu));
    return *(float2*)&r;
}
__device__ __forceinline__ float2 f2add(float2 a, float2 b) {
    u64 r, au = *(u64*)&a, bu = *(u64*)&b;
    asm("add.rn.f32x2 %0,%1,%2;" : "=l"(r) : "l"(au), "l"(bu));
    return *(float2*)&r;
}

// XOR swizzle: conflict-free smem for all structured layouts used below.
__device__ __forceinline__ int phys(int i) {
    return i ^ ((i >> 4) & 15);
}

// Plain single-bit real RY rotation on register-bit BQ (packed).
template<int BQ>
__device__ __forceinline__ void rotY(float2 (&re)[16], float2 (&im)[16],
                                     float2 c, float2 s, float2 ns) {
#pragma unroll
    for (int k0 = 0; k0 < 16; k0++) {
        if (k0 & (1 << BQ)) continue;
        const int k1 = k0 | (1 << BQ);
        const float2 r0 = re[k0], r1 = re[k1], i0 = im[k0], i1 = im[k1];
        re[k0] = f2fma(c, r0, f2mul(ns, r1));
        re[k1] = f2fma(s, r0, f2mul(c,  r1));
        im[k0] = f2fma(c, i0, f2mul(ns, i1));
        im[k1] = f2fma(s, i0, f2mul(c,  i1));
    }
}

__global__ void __launch_bounds__(512, 1)
qc_kernel(const float* __restrict__ x, const float* __restrict__ w,
          float* __restrict__ out)
{
    extern __shared__ float4 st[];                 // 8192 x (re-pack, im-pack) = 128 KB
    __shared__ float2 gc[26], gs[26], gns[26];     // RY coeffs, duplicated packed
    __shared__ __align__(16) float2 tbl0s[16];     // A0 k-delta phases
    __shared__ __align__(16) float2 tbl1s[16];     // D01 k-delta (+Q,R) phases
    __shared__ float2 red[16], red2[16];

    const int t    = threadIdx.x;
    const int b    = blockIdx.x;                   // batch rows 2b, 2b+1
    const int lane = t & 31;
    const int warp = t >> 5;
    const int cbase = warp << 9;

    // ---- tables into smem (disjoint thread groups; visible after BAR1) ----
    if (t < 26) {                                   // RY gate coefficients (precise)
        const int l = t / 13, q = t - l * 13;
        float s, c; sincosf(0.5f * __ldg(&w[l*39 + q*3 + 1]), &s, &c);
        gc[t]  = make_float2( c,  c);
        gs[t]  = make_float2( s,  s);
        gns[t] = make_float2(-s, -s);
    } else if (t >= 64 && t < 80) {                 // A0 delta: i bits 0-3 -> phi0_{12..9}
        const int k = t - 64;
        float ang = 0.f;
        if (k & 1) ang += __ldg(&w[36]);
        if (k & 2) ang += __ldg(&w[33]);
        if (k & 4) ang += __ldg(&w[30]);
        if (k & 8) ang += __ldg(&w[27]);
        float s, c; __sincosf(ang, &s, &c);
        tbl0s[k] = make_float2(c, s);
    } else if (t >= 96 && t < 112) {                // D01 delta: omega0_{3..0} + Q,R terms
        const int k = t - 96;
        float ang = 0.f;
        if (k & 1) ang += __ldg(&w[11]);
        if (k & 2) ang += __ldg(&w[8]);
        if (k & 4) ang += __ldg(&w[5]);
        if (k & 8) ang += __ldg(&w[2]);
        ang += (__popc(k & 14) & 1) ?  0.5f*__ldg(&w[45]) : -0.5f*__ldg(&w[45]);
        ang += (__popc(k & 12) & 1) ?  0.5f*__ldg(&w[42]) : -0.5f*__ldg(&w[42]);
        float s, c; __sincosf(ang, &s, &c);
        tbl1s[k] = make_float2(c, s);
    }

    // ---- load two rows (layout A1: i = (t<<4)|k). Normalization deferred. ----
    float2 re[16], im[16];
    const float4* xp0 = reinterpret_cast<const float4*>(x + (size_t)(2*b)   * DIM + (t << 4));
    const float4* xp1 = reinterpret_cast<const float4*>(x + (size_t)(2*b+1) * DIM + (t << 4));
    float2 ss = make_float2(0.f, 0.f);
#pragma unroll
    for (int k4 = 0; k4 < 4; k4++) {
        const float4 v0 = xp0[k4];
        const float4 v1 = xp1[k4];
        re[k4*4+0] = make_float2(v0.x, v1.x);
        re[k4*4+1] = make_float2(v0.y, v1.y);
        re[k4*4+2] = make_float2(v0.z, v1.z);
        re[k4*4+3] = make_float2(v0.w, v1.w);
    }
#pragma unroll
    for (int k = 0; k < 16; k++) ss = f2fma(re[k], re[k], ss);

    // ---- per-thread phase bases (state-independent; overlaps x-LDG latency) ----
    // A0 base: phi0 over i bits 4-12 (= t bits 0-8) + const for bits 0-3
    float b0a = -0.5f*(__ldg(&w[27]) + __ldg(&w[30]) + __ldg(&w[33]) + __ldg(&w[36]));
#pragma unroll
    for (int q = 0; q < 9; q++) {
        const float ph = __ldg(&w[3*q]);
        b0a += ((t >> (8 - q)) & 1) ? 0.5f*ph : -0.5f*ph;
    }
    float sb0, cb0; __sincosf(b0a, &sb0, &cb0);     // TB0 = e^{i base0}

    // D01 base (C' layout: pt = (lane<<4)|warp = i bits 0-8):
    const int pt = (lane << 4) | warp;
    // baseB: omega0 over i bits 0-8, + const for bits 9-12
    float bBa = -0.5f*(__ldg(&w[2]) + __ldg(&w[5]) + __ldg(&w[8]) + __ldg(&w[11]));
#pragma unroll
    for (int bb = 0; bb < 9; bb++) {
        const float om = __ldg(&w[3*(12 - bb) + 2]);
        bBa += ((pt >> bb) & 1) ? 0.5f*om : -0.5f*om;
    }
    // P(pt) = sum_{t=0..9} (-0.5 phi1_{12-t}) * sign(parity(pm_t & pt))
    const int PM[10] = {511,510,508,504,496,480,448,384,256,0};
    float Pv = 0.f;
#pragma unroll
    for (int tt = 0; tt < 10; tt++) {
        const float ph = __ldg(&w[75 - 3*tt]);
        Pv += (__popc(PM[tt] & pt) & 1) ? 0.5f*ph : -0.5f*ph;
    }
    const float Sv = (__popc(pt) & 1) ? 0.5f*__ldg(&w[39]) : -0.5f*__ldg(&w[39]);
    float sB, cB; __sincosf(bBa, &sB, &cB);
    float sP, cP; __sincosf(Pv,  &sP, &cP);
    float sS, cS; __sincosf(Sv,  &sS, &cS);
    // W[s1][s2] = e^{i baseB} * e^{+-iP} * e^{+-iS}
    const float t1r = cB*cP - sB*sP, t1i = cB*sP + sB*cP;   // * e^{+iP}
    const float t2r = cB*cP + sB*sP, t2i = sB*cP - cB*sP;   // * e^{-iP}
    const float w00r = t1r*cS - t1i*sS, w00i = t1r*sS + t1i*cS;
    const float w01r = t1r*cS + t1i*sS, w01i = t1i*cS - t1r*sS;
    const float w10r = t2r*cS - t2i*sS, w10i = t2r*sS + t2i*cS;
    const float w11r = t2r*cS + t2i*sS, w11i = t2i*cS - t2r*sS;

    __syncthreads();   // BAR 1: tables visible (hidden under x-load latency)

    // ---- A0: layer-0 phi phase on the (unnormalized) real input ----
    const float4* tbl0f4 = reinterpret_cast<const float4*>(tbl0s);
#pragma unroll
    for (int kk = 0; kk < 8; kk++) {
        const float4 tb = tbl0f4[kk];
        {
            const int k0 = 2*kk;
            const float vr = cb0*tb.x - sb0*tb.y;
            const float vi = cb0*tb.y + sb0*tb.x;
            const float2 x0 = re[k0];
            re[k0] = f2mul(x0, make_float2(vr, vr));
            im[k0] = f2mul(x0, make_float2(vi, vi));
        }
        {
            const int k1 = 2*kk + 1;
            const float vr = cb0*tb.z - sb0*tb.w;
            const float vi = cb0*tb.w + sb0*tb.z;
            const float2 x1 = re[k1];
            re[k1] = f2mul(x1, make_float2(vr, vr));
            im[k1] = f2mul(x1, make_float2(vi, vi));
        }
    }

    // ==== LAYER 0 ====
    // pass A1: reg bits = i bits 0-3 (qubits 12..9)
    rotY<0>(re, im, gc[12], gs[12], gns[12]);
    rotY<1>(re, im, gc[11], gs[11], gns[11]);
    rotY<2>(re, im, gc[10], gs[10], gns[10]);
    rotY<3>(re, im, gc[ 9], gs[ 9], gns[ 9]);

    // warp-local exchange A1 -> A2 (reg bits = i bits 4-7)
    const int a2base = cbase | ((lane & 16) << 4) | (lane & 15);
#pragma unroll
    for (int k = 0; k < 16; k++)
        st[phys(cbase | (lane << 4) | k)] = make_float4(re[k].x, re[k].y, im[k].x, im[k].y);
    __syncwarp();
#pragma unroll
    for (int k = 0; k < 16; k++) {
        const float4 v = st[phys(a2base | (k << 4))];
        re[k] = make_float2(v.x, v.y); im[k] = make_float2(v.z, v.w);
    }
    rotY<0>(re, im, gc[8], gs[8], gns[8]);
    rotY<1>(re, im, gc[7], gs[7], gns[7]);
    rotY<2>(re, im, gc[6], gs[6], gns[6]);
    rotY<3>(re, im, gc[5], gs[5], gns[5]);
    // shfl gate on i bit 8 (= lane bit 4), qubit 4
    {
        const float2 cg   = gc[4];
        const float2 sSel = (lane & 16) ? gs[4] : gns[4];
#pragma unroll
        for (int k = 0; k < 16; k++) {
            const u64 pr = __shfl_xor_sync(0xffffffffu, *(u64*)&re[k], 16);
            const u64 pi = __shfl_xor_sync(0xffffffffu, *(u64*)&im[k], 16);
            re[k] = f2fma(cg, re[k], f2mul(sSel, *(const float2*)&pr));
            im[k] = f2fma(cg, im[k], f2mul(sSel, *(const float2*)&pi));
        }
    }

    // block exchange A2 -> C' : i = (k<<9) | pt
#pragma unroll
    for (int k = 0; k < 16; k++)
        st[phys(a2base | (k << 4))] = make_float4(re[k].x, re[k].y, im[k].x, im[k].y);
    __syncthreads();                                             // BAR 2
#pragma unroll
    for (int k = 0; k < 16; k++) {
        const float4 v = st[phys((k << 9) | pt)];
        re[k] = make_float2(v.x, v.y); im[k] = make_float2(v.z, v.w);
    }
    // pass C': reg bits = i bits 9-12 (qubits 3..0)
    rotY<0>(re, im, gc[3], gs[3], gns[3]);
    rotY<1>(re, im, gc[2], gs[2], gns[2]);
    rotY<2>(re, im, gc[1], gs[1], gns[1]);
    rotY<3>(re, im, gc[0], gs[0], gns[0]);

    // ==== D01 diagonal: V[k] = W[s1(k)][s2(k)] * tbl1s[k] ====
    const float4* tbl1f4 = reinterpret_cast<const float4*>(tbl1s);
#pragma unroll
    for (int kk = 0; kk < 8; kk++) {
        const float4 tb = tbl1f4[kk];
#pragma unroll
        for (int h = 0; h < 2; h++) {
            const int k = 2*kk + h;
            const float tr_ = h ? tb.z : tb.x;
            const float ti_ = h ? tb.w : tb.y;
            const int s1 = __popc(k) & 1;
            const int s2 = __popc(k & 7) & 1;
            const float wr = s1 ? (s2 ? w11r : w10r) : (s2 ? w01r : w00r);
            const float wi = s1 ? (s2 ? w11i : w10i) : (s2 ? w01i : w00i);
            const float vr = wr*tr_ - wi*ti_;
            const float vi = wr*ti_ + wi*tr_;
            const float2 cd = make_float2(vr, vr);
            const float2 sd = make_float2(vi, vi);
            const float2 nd = make_float2(-vi, -vi);
            const float2 nr = f2fma(cd, re[k], f2mul(nd, im[k]));
            const float2 ni = f2fma(sd, re[k], f2mul(cd, im[k]));
            re[k] = nr; im[k] = ni;
        }
    }

    // ==== LAYER 1: the 4 observable-relevant gates, conjugated by M0 ====
    // d12 = {11,12} (k-mask 12), orient = parity(i & 4095) : gate 13 (qubit 0)
    {
        const int Pt = __popc(pt) & 1;
        const float2 c = gc[13];
#pragma unroll
        for (int k0 = 0; k0 < 8; k0++) {
            const int k1 = k0 ^ 12;
            const int o = Pt ^ (__popc(k0 & 7) & 1);
            const float2 sa = o ? gs[13] : gns[13];
            const float2 sb = o ? gns[13] : gs[13];
            const float2 ar = re[k0], ai = im[k0], br = re[k1], bi = im[k1];
            re[k0] = f2fma(c, ar, f2mul(sa, br));
            im[k0] = f2fma(c, ai, f2mul(sa, bi));
            re[k1] = f2fma(c, br, f2mul(sb, ar));
            im[k1] = f2fma(c, bi, f2mul(sb, ai));
        }
    }
    // d10 = {9,10} (k-mask 3), orient = parity(k & 14) : gate 15 (qubit 2)
    {
        const float2 c = gc[15];
#pragma unroll
        for (int k0 = 0; k0 < 16; k0++) {
            if ((k0 & 3) > 1) continue;
            const int k1 = k0 ^ 3;
            const int o = __popc(k0 & 14) & 1;
            const float2 sa = o ? gs[15] : gns[15];
            const float2 sb = o ? gns[15] : gs[15];
            const float2 ar = re[k0], ai = im[k0], br = re[k1], bi = im[k1];
            re[k0] = f2fma(c, ar, f2mul(sa, br));
            im[k0] = f2fma(c, ai, f2mul(sa, bi));
            re[k1] = f2fma(c, br, f2mul(sb, ar));
            im[k1] = f2fma(c, bi, f2mul(sb, ai));
        }
    }
    // d8 = {7,8} (lane-mask 24, shfl), orient = lane bit4 ^ parity(k) : gate 17 (qubit 4)
    {
        const float2 c = gc[17];
        const int oL = (lane >> 4) & 1;
        const float2 sEv = oL ? gs[17] : gns[17];
        const float2 sOd = oL ? gns[17] : gs[17];
#pragma unroll
        for (int k = 0; k < 16; k++) {
            const u64 pr = __shfl_xor_sync(0xffffffffu, *(u64*)&re[k], 24);
            const u64 pi = __shfl_xor_sync(0xffffffffu, *(u64*)&im[k], 24);
            const float2 sc = (__popc(k) & 1) ? sOd : sEv;
            re[k] = f2fma(c, re[k], f2mul(sc, *(const float2*)&pr));
            im[k] = f2fma(c, im[k], f2mul(sc, *(const float2*)&pi));
        }
    }
    // d6 = {5,6} (lane-mask 6, shfl), orient = parity(lane&28) ^ parity(k) : gate 19 (qubit 6)
    {
        const float2 c = gc[19];
        const int oL = __popc(lane & 28) & 1;
        const float2 sEv = oL ? gs[19] : gns[19];
        const float2 sOd = oL ? gns[19] : gs[19];
#pragma unroll
        for (int k = 0; k < 16; k++) {
            const u64 pr = __shfl_xor_sync(0xffffffffu, *(u64*)&re[k], 6);
            const u64 pi = __shfl_xor_sync(0xffffffffu, *(u64*)&im[k], 6);
            const float2 sc = (__popc(k) & 1) ? sOd : sEv;
            re[k] = f2fma(c, re[k], f2mul(sc, *(const float2*)&pr));
            im[k] = f2fma(c, im[k], f2mul(sc, *(const float2*)&pi));
        }
    }

    // ==== measurement: sign = parity(i & 4927) in i-space ====
    const float2 mn1 = make_float2(-1.f, -1.f);
    const int sgt = (__popc(lane & 19) + __popc(warp)) & 1;
    float2 acc = make_float2(0.f, 0.f);
#pragma unroll
    for (int k = 0; k < 16; k++) {
        const float2 p = f2fma(re[k], re[k], f2mul(im[k], im[k]));
        if (__popc(k & 9) & 1) acc = f2fma(p, mn1, acc);
        else                   acc = f2add(acc, p);
    }
    if (sgt) acc = f2mul(acc, mn1);
    // joint reduction of the signed sum and ||x||^2
#pragma unroll
    for (int o = 16; o > 0; o >>= 1) {
        u64 av = *(u64*)&acc;
        u64 ov = __shfl_xor_sync(0xffffffffu, av, o);
        acc = f2add(acc, *(float2*)&ov);
        u64 sv = *(u64*)&ss;
        u64 so = __shfl_xor_sync(0xffffffffu, sv, o);
        ss = f2add(ss, *(float2*)&so);
    }
    if (lane == 0) { red[warp] = acc; red2[warp] = ss; }
    __syncthreads();                                             // BAR 3
    if (t == 0) {
        float2 ta = make_float2(0.f, 0.f);
        float2 ts = make_float2(0.f, 0.f);
#pragma unroll
        for (int r = 0; r < 16; r++) { ta = f2add(ta, red[r]); ts = f2add(ts, red2[r]); }
        out[2*b]   = ta.x / ts.x;
        out[2*b+1] = ta.y / ts.y;
    }
}

extern "C" void kernel_launch(void* const* d_in, const int* in_sizes, int n_in,
                              void* d_out, int out_size)
{
    const float* x = (const float*)d_in[0];
    const float* w = (const float*)d_in[1];
    float* out = (float*)d_out;
    const int B2 = (in_sizes[0] / DIM) / 2;        // 2 batch rows per CTA

    const size_t shmem = DIM * sizeof(float4);     // 128 KB
    cudaFuncSetAttribute(qc_kernel, cudaFuncAttributeMaxDynamicSharedMemorySize,
                         (int)shmem);
    qc_kernel<<<B2, 512, shmem>>>(x, w, out);      // single kernel: no setup launch
}

// round 13
// speedup vs baseline: 1.6222x; 1.1000x over previous
#include <cuda_runtime.h>

#define DIM 8192
typedef unsigned long long u64;

// ---- packed f32x2 helpers (SASS FFMA2/FMUL2 path, PTX-only) ----
__device__ __forceinline__ float2 f2fma(float2 a, float2 b, float2 c) {
    u64 r, au = *(u64*)&a, bu = *(u64*)&b, cu = *(u64*)&c;
    asm("fma.rn.f32x2 %0,%1,%2,%3;" : "=l"(r) : "l"(au), "l"(bu), "l"(cu));
    return *(float2*)&r;
}
__device__ __forceinline__ float2 f2mul(float2 a, float2 b) {
    u64 r, au = *(u64*)&a, bu = *(u64*)&b;
    asm("mul.rn.f32x2 %0,%1,%2;" : "=l"(r) : "l"(au), "l"(bu));
    return *(float2*)&r;
}
__device__ __forceinline__ float2 f2add(float2 a, float2 b) {
    u64 r, au = *(u64*)&a, bu = *(u64*)&b;
    asm("add.rn.f32x2 %0,%1,%2;" : "=l"(r) : "l"(au), "l"(bu));
    return *(float2*)&r;
}

// XOR swizzle: conflict-free smem for all structured layouts used below.
__device__ __forceinline__ int phys(int i) {
    return i ^ ((i >> 4) & 15);
}

// Tangent-form RY rotation on register-bit BQ: out = (I + t*J) * in.
// The per-gate scalar c = cos(theta/2) is DEFERRED into one global constant
// C = prod(c_g) applied at the measurement (amp enters only as C^2*|amp|^2).
template<int BQ>
__device__ __forceinline__ void rotYt(float2 (&re)[16], float2 (&im)[16],
                                      float2 tg, float2 ntg) {
#pragma unroll
    for (int k0 = 0; k0 < 16; k0++) {
        if (k0 & (1 << BQ)) continue;
        const int k1 = k0 | (1 << BQ);
        const float2 r0 = re[k0], r1 = re[k1], i0 = im[k0], i1 = im[k1];
        re[k0] = f2fma(ntg, r1, r0);
        re[k1] = f2fma(tg,  r0, r1);
        im[k0] = f2fma(ntg, i1, i0);
        im[k1] = f2fma(tg,  i0, i1);
    }
}

__global__ void __launch_bounds__(512, 1)
qc_kernel(const float* __restrict__ x, const float* __restrict__ w,
          float* __restrict__ out)
{
    extern __shared__ float4 st[];                 // 8192 x (re-pack, im-pack) = 128 KB
    __shared__ float2 gt[26], gnt[26];             // tan(theta/2), packed dup (+/-)
    __shared__ float  gcs[26];                     // cos(theta/2) scalars (final C)
    __shared__ __align__(16) float2 tbl0s[16];     // A0 k-delta phases
    __shared__ __align__(16) float2 tbl1s[16];     // D01 k-delta (+Q,R) phases
    __shared__ float2 red[16], red2[16];

    const int t    = threadIdx.x;
    const int b    = blockIdx.x;                   // batch rows 2b, 2b+1
    const int lane = t & 31;
    const int warp = t >> 5;
    const int cbase = warp << 9;

    // ---- tables into smem (disjoint thread groups; visible after BAR1) ----
    if (t < 26) {                                   // RY gate coefficients
        const int l = t / 13, q = t - l * 13;
        float s, c; sincosf(0.5f * __ldg(&w[l*39 + q*3 + 1]), &s, &c);
        const float tn = s / c;                     // IEEE divide (precise)
        gt[t]  = make_float2( tn,  tn);
        gnt[t] = make_float2(-tn, -tn);
        gcs[t] = c;
    } else if (t >= 64 && t < 80) {                 // A0 delta: i bits 0-3 -> phi0_{12..9}
        const int k = t - 64;
        float ang = 0.f;
        if (k & 1) ang += __ldg(&w[36]);
        if (k & 2) ang += __ldg(&w[33]);
        if (k & 4) ang += __ldg(&w[30]);
        if (k & 8) ang += __ldg(&w[27]);
        float s, c; __sincosf(ang, &s, &c);
        tbl0s[k] = make_float2(c, s);
    } else if (t >= 96 && t < 112) {                // D01 delta: omega0_{3..0} + Q,R terms
        const int k = t - 96;
        float ang = 0.f;
        if (k & 1) ang += __ldg(&w[11]);
        if (k & 2) ang += __ldg(&w[8]);
        if (k & 4) ang += __ldg(&w[5]);
        if (k & 8) ang += __ldg(&w[2]);
        ang += (__popc(k & 14) & 1) ?  0.5f*__ldg(&w[45]) : -0.5f*__ldg(&w[45]);
        ang += (__popc(k & 12) & 1) ?  0.5f*__ldg(&w[42]) : -0.5f*__ldg(&w[42]);
        float s, c; __sincosf(ang, &s, &c);
        tbl1s[k] = make_float2(c, s);
    }

    // ---- load two rows (layout A1: i = (t<<4)|k). Normalization deferred. ----
    float2 re[16], im[16];
    const float4* xp0 = reinterpret_cast<const float4*>(x + (size_t)(2*b)   * DIM + (t << 4));
    const float4* xp1 = reinterpret_cast<const float4*>(x + (size_t)(2*b+1) * DIM + (t << 4));
    float2 ss = make_float2(0.f, 0.f);
#pragma unroll
    for (int k4 = 0; k4 < 4; k4++) {
        const float4 v0 = xp0[k4];
        const float4 v1 = xp1[k4];
        re[k4*4+0] = make_float2(v0.x, v1.x);
        re[k4*4+1] = make_float2(v0.y, v1.y);
        re[k4*4+2] = make_float2(v0.z, v1.z);
        re[k4*4+3] = make_float2(v0.w, v1.w);
    }
#pragma unroll
    for (int k = 0; k < 16; k++) ss = f2fma(re[k], re[k], ss);

    // ---- per-thread phase bases (state-independent; overlaps x-LDG latency) ----
    float b0a = -0.5f*(__ldg(&w[27]) + __ldg(&w[30]) + __ldg(&w[33]) + __ldg(&w[36]));
#pragma unroll
    for (int q = 0; q < 9; q++) {
        const float ph = __ldg(&w[3*q]);
        b0a += ((t >> (8 - q)) & 1) ? 0.5f*ph : -0.5f*ph;
    }
    float sb0, cb0; __sincosf(b0a, &sb0, &cb0);

    const int pt = (lane << 4) | warp;
    float bBa = -0.5f*(__ldg(&w[2]) + __ldg(&w[5]) + __ldg(&w[8]) + __ldg(&w[11]));
#pragma unroll
    for (int bb = 0; bb < 9; bb++) {
        const float om = __ldg(&w[3*(12 - bb) + 2]);
        bBa += ((pt >> bb) & 1) ? 0.5f*om : -0.5f*om;
    }
    const int PM[10] = {511,510,508,504,496,480,448,384,256,0};
    float Pv = 0.f;
#pragma unroll
    for (int tt = 0; tt < 10; tt++) {
        const float ph = __ldg(&w[75 - 3*tt]);
        Pv += (__popc(PM[tt] & pt) & 1) ? 0.5f*ph : -0.5f*ph;
    }
    const float Sv = (__popc(pt) & 1) ? 0.5f*__ldg(&w[39]) : -0.5f*__ldg(&w[39]);
    float sB, cB; __sincosf(bBa, &sB, &cB);
    float sP, cP; __sincosf(Pv,  &sP, &cP);
    float sS, cS; __sincosf(Sv,  &sS, &cS);
    const float t1r = cB*cP - sB*sP, t1i = cB*sP + sB*cP;
    const float t2r = cB*cP + sB*sP, t2i = sB*cP - cB*sP;
    const float w00r = t1r*cS - t1i*sS, w00i = t1r*sS + t1i*cS;
    const float w01r = t1r*cS + t1i*sS, w01i = t1i*cS - t1r*sS;
    const float w10r = t2r*cS - t2i*sS, w10i = t2r*sS + t2i*cS;
    const float w11r = t2r*cS + t2i*sS, w11i = t2i*cS - t2r*sS;

    __syncthreads();   // BAR 1: tables visible (hidden under x-load latency)

    // ---- A0: layer-0 phi phase on the (unnormalized) real input ----
    const float4* tbl0f4 = reinterpret_cast<const float4*>(tbl0s);
#pragma unroll
    for (int kk = 0; kk < 8; kk++) {
        const float4 tb = tbl0f4[kk];
        {
            const int k0 = 2*kk;
            const float vr = cb0*tb.x - sb0*tb.y;
            const float vi = cb0*tb.y + sb0*tb.x;
            const float2 x0 = re[k0];
            re[k0] = f2mul(x0, make_float2(vr, vr));
            im[k0] = f2mul(x0, make_float2(vi, vi));
        }
        {
            const int k1 = 2*kk + 1;
            const float vr = cb0*tb.z - sb0*tb.w;
            const float vi = cb0*tb.w + sb0*tb.z;
            const float2 x1 = re[k1];
            re[k1] = f2mul(x1, make_float2(vr, vr));
            im[k1] = f2mul(x1, make_float2(vi, vi));
        }
    }

    // ==== LAYER 0 (tangent form; c-factors deferred to C) ====
    // pass A1: reg bits = i bits 0-3 (qubits 12..9)
    rotYt<0>(re, im, gt[12], gnt[12]);
    rotYt<1>(re, im, gt[11], gnt[11]);
    rotYt<2>(re, im, gt[10], gnt[10]);
    rotYt<3>(re, im, gt[ 9], gnt[ 9]);

    // warp-local exchange A1 -> A2 (reg bits = i bits 4-7)
    const int a2base = cbase | ((lane & 16) << 4) | (lane & 15);
#pragma unroll
    for (int k = 0; k < 16; k++)
        st[phys(cbase | (lane << 4) | k)] = make_float4(re[k].x, re[k].y, im[k].x, im[k].y);
    __syncwarp();
#pragma unroll
    for (int k = 0; k < 16; k++) {
        const float4 v = st[phys(a2base | (k << 4))];
        re[k] = make_float2(v.x, v.y); im[k] = make_float2(v.z, v.w);
    }
    rotYt<0>(re, im, gt[8], gnt[8]);
    rotYt<1>(re, im, gt[7], gnt[7]);
    rotYt<2>(re, im, gt[6], gnt[6]);
    rotYt<3>(re, im, gt[5], gnt[5]);
    // shfl gate on i bit 8 (= lane bit 4), qubit 4: out = amp + (+-t)*partner
    {
        const float2 tSel = (lane & 16) ? gt[4] : gnt[4];
#pragma unroll
        for (int k = 0; k < 16; k++) {
            const u64 pr = __shfl_xor_sync(0xffffffffu, *(u64*)&re[k], 16);
            const u64 pi = __shfl_xor_sync(0xffffffffu, *(u64*)&im[k], 16);
            re[k] = f2fma(tSel, *(const float2*)&pr, re[k]);
            im[k] = f2fma(tSel, *(const float2*)&pi, im[k]);
        }
    }

    // block exchange A2 -> C' : i = (k<<9) | pt
#pragma unroll
    for (int k = 0; k < 16; k++)
        st[phys(a2base | (k << 4))] = make_float4(re[k].x, re[k].y, im[k].x, im[k].y);
    __syncthreads();                                             // BAR 2
#pragma unroll
    for (int k = 0; k < 16; k++) {
        const float4 v = st[phys((k << 9) | pt)];
        re[k] = make_float2(v.x, v.y); im[k] = make_float2(v.z, v.w);
    }
    // pass C': reg bits = i bits 9-12 (qubits 3..0)
    rotYt<0>(re, im, gt[3], gnt[3]);
    rotYt<1>(re, im, gt[2], gnt[2]);
    rotYt<2>(re, im, gt[1], gnt[1]);
    rotYt<3>(re, im, gt[0], gnt[0]);

    // ==== D01 diagonal: V[k] = W[s1(k)][s2(k)] * tbl1s[k] (unit phase, exact) ====
    const float4* tbl1f4 = reinterpret_cast<const float4*>(tbl1s);
#pragma unroll
    for (int kk = 0; kk < 8; kk++) {
        const float4 tb = tbl1f4[kk];
#pragma unroll
        for (int h = 0; h < 2; h++) {
            const int k = 2*kk + h;
            const float tr_ = h ? tb.z : tb.x;
            const float ti_ = h ? tb.w : tb.y;
            const int s1 = __popc(k) & 1;
            const int s2 = __popc(k & 7) & 1;
            const float wr = s1 ? (s2 ? w11r : w10r) : (s2 ? w01r : w00r);
            const float wi = s1 ? (s2 ? w11i : w10i) : (s2 ? w01i : w00i);
            const float vr = wr*tr_ - wi*ti_;
            const float vi = wr*ti_ + wi*tr_;
            const float2 cd = make_float2(vr, vr);
            const float2 sd = make_float2(vi, vi);
            const float2 nd = make_float2(-vi, -vi);
            const float2 nr = f2fma(cd, re[k], f2mul(nd, im[k]));
            const float2 ni = f2fma(sd, re[k], f2mul(cd, im[k]));
            re[k] = nr; im[k] = ni;
        }
    }

    // ==== LAYER 1: 4 observable-relevant gates (tangent form) ====
    // d12 = {11,12} (k-mask 12), orient = parity(i & 4095) : gate 13 (qubit 0)
    {
        const int Pt = __popc(pt) & 1;
#pragma unroll
        for (int k0 = 0; k0 < 8; k0++) {
            const int k1 = k0 ^ 12;
            const int o = Pt ^ (__popc(k0 & 7) & 1);
            const float2 ta_ = o ? gt[13] : gnt[13];
            const float2 tb_ = o ? gnt[13] : gt[13];
            const float2 ar = re[k0], ai = im[k0], br = re[k1], bi = im[k1];
            re[k0] = f2fma(ta_, br, ar);
            im[k0] = f2fma(ta_, bi, ai);
            re[k1] = f2fma(tb_, ar, br);
            im[k1] = f2fma(tb_, ai, bi);
        }
    }
    // d10 = {9,10} (k-mask 3), orient = parity(k & 14) : gate 15 (qubit 2)
    {
#pragma unroll
        for (int k0 = 0; k0 < 16; k0++) {
            if ((k0 & 3) > 1) continue;
            const int k1 = k0 ^ 3;
            const int o = __popc(k0 & 14) & 1;
            const float2 ta_ = o ? gt[15] : gnt[15];
            const float2 tb_ = o ? gnt[15] : gt[15];
            const float2 ar = re[k0], ai = im[k0], br = re[k1], bi = im[k1];
            re[k0] = f2fma(ta_, br, ar);
            im[k0] = f2fma(ta_, bi, ai);
            re[k1] = f2fma(tb_, ar, br);
            im[k1] = f2fma(tb_, ai, bi);
        }
    }
    // d8 = {7,8} (lane-mask 24, shfl), orient = lane bit4 ^ parity(k) : gate 17 (qubit 4)
    {
        const int oL = (lane >> 4) & 1;
        const float2 tEv = oL ? gt[17] : gnt[17];
        const float2 tOd = oL ? gnt[17] : gt[17];
#pragma unroll
        for (int k = 0; k < 16; k++) {
            const u64 pr = __shfl_xor_sync(0xffffffffu, *(u64*)&re[k], 24);
            const u64 pi = __shfl_xor_sync(0xffffffffu, *(u64*)&im[k], 24);
            const float2 tc = (__popc(k) & 1) ? tOd : tEv;
            re[k] = f2fma(tc, *(const float2*)&pr, re[k]);
            im[k] = f2fma(tc, *(const float2*)&pi, im[k]);
        }
    }
    // d6 = {5,6} (lane-mask 6, shfl), orient = parity(lane&28) ^ parity(k) : gate 19 (qubit 6)
    {
        const int oL = __popc(lane & 28) & 1;
        const float2 tEv = oL ? gt[19] : gnt[19];
        const float2 tOd = oL ? gnt[19] : gt[19];
#pragma unroll
        for (int k = 0; k < 16; k++) {
            const u64 pr = __shfl_xor_sync(0xffffffffu, *(u64*)&re[k], 6);
            const u64 pi = __shfl_xor_sync(0xffffffffu, *(u64*)&im[k], 6);
            const float2 tc = (__popc(k) & 1) ? tOd : tEv;
            re[k] = f2fma(tc, *(const float2*)&pr, re[k]);
            im[k] = f2fma(tc, *(const float2*)&pi, im[k]);
        }
    }

    // ==== measurement: sign = parity(i & 4927); scaling by C^2 deferred ====
    const float2 mn1 = make_float2(-1.f, -1.f);
    const int sgt = (__popc(lane & 19) + __popc(warp)) & 1;
    float2 acc = make_float2(0.f, 0.f);
#pragma unroll
    for (int k = 0; k < 16; k++) {
        const float2 p = f2fma(re[k], re[k], f2mul(im[k], im[k]));
        if (__popc(k & 9) & 1) acc = f2fma(p, mn1, acc);
        else                   acc = f2add(acc, p);
    }
    if (sgt) acc = f2mul(acc, mn1);
#pragma unroll
    for (int o = 16; o > 0; o >>= 1) {
        u64 av = *(u64*)&acc;
        u64 ov = __shfl_xor_sync(0xffffffffu, av, o);
        acc = f2add(acc, *(float2*)&ov);
        u64 sv = *(u64*)&ss;
        u64 so = __shfl_xor_sync(0xffffffffu, sv, o);
        ss = f2add(ss, *(float2*)&so);
    }
    if (lane == 0) { red[warp] = acc; red2[warp] = ss; }
    __syncthreads();                                             // BAR 3
    if (t == 0) {
        float2 ta = make_float2(0.f, 0.f);
        float2 ts = make_float2(0.f, 0.f);
#pragma unroll
        for (int r = 0; r < 16; r++) { ta = f2add(ta, red[r]); ts = f2add(ts, red2[r]); }
        // C = product of deferred cosines over the 17 applied gates
        float C = 1.f;
#pragma unroll
        for (int g = 0; g < 13; g++) C *= gcs[g];
        C *= gcs[13] * gcs[15] * gcs[17] * gcs[19];
        const float C2 = C * C;
        out[2*b]   = C2 * ta.x / ts.x;
        out[2*b+1] = C2 * ta.y / ts.y;
    }
}

extern "C" void kernel_launch(void* const* d_in, const int* in_sizes, int n_in,
                              void* d_out, int out_size)
{
    const float* x = (const float*)d_in[0];
    const float* w = (const float*)d_in[1];
    float* out = (float*)d_out;
    const int B2 = (in_sizes[0] / DIM) / 2;        // 2 batch rows per CTA

    const size_t shmem = DIM * sizeof(float4);     // 128 KB
    cudaFuncSetAttribute(qc_kernel, cudaFuncAttributeMaxDynamicSharedMemorySize,
                         (int)shmem);
    qc_kernel<<<B2, 512, shmem>>>(x, w, out);      // single kernel
}

// round 14
// speedup vs baseline: 1.6245x; 1.0014x over previous
#include <cuda_runtime.h>

#define DIM 8192
typedef unsigned long long u64;

// ---- packed f32x2 helpers (SASS FFMA2/FMUL2 path, PTX-only) ----
__device__ __forceinline__ float2 f2fma(float2 a, float2 b, float2 c) {
    u64 r, au = *(u64*)&a, bu = *(u64*)&b, cu = *(u64*)&c;
    asm("fma.rn.f32x2 %0,%1,%2,%3;" : "=l"(r) : "l"(au), "l"(bu), "l"(cu));
    return *(float2*)&r;
}
__device__ __forceinline__ float2 f2mul(float2 a, float2 b) {
    u64 r, au = *(u64*)&a, bu = *(u64*)&b;
    asm("mul.rn.f32x2 %0,%1,%2;" : "=l"(r) : "l"(au), "l"(bu));
    return *(float2*)&r;
}
__device__ __forceinline__ float2 f2add(float2 a, float2 b) {
    u64 r, au = *(u64*)&a, bu = *(u64*)&b;
    asm("add.rn.f32x2 %0,%1,%2;" : "=l"(r) : "l"(au), "l"(bu));
    return *(float2*)&r;
}

// XOR-linear swizzle; bank(16B) = i0-2 ^ i4-6 ^ (i9<<1 | i10<<2).
// Verified conflict-free for all 6 structured access patterns below.
// XOR-linear over disjoint fields => phys(a|b) = phys(a) ^ phys(b).
__device__ constexpr int phys(int i) {
    return i ^ ((i >> 4) & 15) ^ ((i >> 8) & 6);
}

// Tangent-form RY rotation on register-bit BQ: out = (I + t*J) * in.
// Per-gate c = cos(theta/2) deferred into global C applied at measurement.
template<int BQ>
__device__ __forceinline__ void rotYt(float2 (&re)[16], float2 (&im)[16],
                                      float2 tg, float2 ntg) {
#pragma unroll
    for (int k0 = 0; k0 < 16; k0++) {
        if (k0 & (1 << BQ)) continue;
        const int k1 = k0 | (1 << BQ);
        const float2 r0 = re[k0], r1 = re[k1], i0 = im[k0], i1 = im[k1];
        re[k0] = f2fma(ntg, r1, r0);
        re[k1] = f2fma(tg,  r0, r1);
        im[k0] = f2fma(ntg, i1, i0);
        im[k1] = f2fma(tg,  i0, i1);
    }
}

__global__ void __launch_bounds__(512, 1)
qc_kernel(const float* __restrict__ x, const float* __restrict__ w,
          float* __restrict__ out)
{
    extern __shared__ float4 st[];                 // 8192 x (re-pack, im-pack) = 128 KB
    __shared__ float2 gt[26], gnt[26];             // tan(theta/2), packed dup (+/-)
    __shared__ float  gcs[26];                     // cos(theta/2) scalars (final C)
    __shared__ __align__(16) float2 tbl0s[16];     // A0 k-delta phases
    __shared__ __align__(16) float2 tbl1s[16];     // D01 k-delta (+Q,R) phases
    __shared__ float2 red[16], red2[16];

    const int t    = threadIdx.x;
    const int b    = blockIdx.x;                   // batch rows 2b, 2b+1
    const int lane = t & 31;
    const int warp = t >> 5;

    // ---- tables into smem (disjoint thread groups; visible after BAR1) ----
    if (t < 26) {
        const int l = t / 13, q = t - l * 13;
        float s, c; sincosf(0.5f * __ldg(&w[l*39 + q*3 + 1]), &s, &c);
        const float tn = s / c;
        gt[t]  = make_float2( tn,  tn);
        gnt[t] = make_float2(-tn, -tn);
        gcs[t] = c;
    } else if (t >= 64 && t < 80) {                 // A0 delta: i bits 0-3 -> phi0_{12..9}
        const int k = t - 64;
        float ang = 0.f;
        if (k & 1) ang += __ldg(&w[36]);
        if (k & 2) ang += __ldg(&w[33]);
        if (k & 4) ang += __ldg(&w[30]);
        if (k & 8) ang += __ldg(&w[27]);
        float s, c; __sincosf(ang, &s, &c);
        tbl0s[k] = make_float2(c, s);
    } else if (t >= 96 && t < 112) {                // D01 delta: omega0_{3..0} + Q,R terms
        const int k = t - 96;
        float ang = 0.f;
        if (k & 1) ang += __ldg(&w[11]);
        if (k & 2) ang += __ldg(&w[8]);
        if (k & 4) ang += __ldg(&w[5]);
        if (k & 8) ang += __ldg(&w[2]);
        ang += (__popc(k & 14) & 1) ?  0.5f*__ldg(&w[45]) : -0.5f*__ldg(&w[45]);
        ang += (__popc(k & 12) & 1) ?  0.5f*__ldg(&w[42]) : -0.5f*__ldg(&w[42]);
        float s, c; __sincosf(ang, &s, &c);
        tbl1s[k] = make_float2(c, s);
    }

    // ---- load two rows (layout A1: i = (t<<4)|k). Normalization deferred. ----
    float2 re[16], im[16];
    const float4* xp0 = reinterpret_cast<const float4*>(x + (size_t)(2*b)   * DIM + (t << 4));
    const float4* xp1 = reinterpret_cast<const float4*>(x + (size_t)(2*b+1) * DIM + (t << 4));
    float2 ss = make_float2(0.f, 0.f);
#pragma unroll
    for (int k4 = 0; k4 < 4; k4++) {
        const float4 v0 = xp0[k4];
        const float4 v1 = xp1[k4];
        re[k4*4+0] = make_float2(v0.x, v1.x);
        re[k4*4+1] = make_float2(v0.y, v1.y);
        re[k4*4+2] = make_float2(v0.z, v1.z);
        re[k4*4+3] = make_float2(v0.w, v1.w);
    }
#pragma unroll
    for (int k = 0; k < 16; k++) ss = f2fma(re[k], re[k], ss);

    // ---- per-thread phase bases (overlaps x-LDG latency) ----
    float b0a = -0.5f*(__ldg(&w[27]) + __ldg(&w[30]) + __ldg(&w[33]) + __ldg(&w[36]));
#pragma unroll
    for (int q = 0; q < 9; q++) {
        const float ph = __ldg(&w[3*q]);
        b0a += ((t >> (8 - q)) & 1) ? 0.5f*ph : -0.5f*ph;
    }
    float sb0, cb0; __sincosf(b0a, &sb0, &cb0);

    const int pt = (lane << 4) | warp;
    float bBa = -0.5f*(__ldg(&w[2]) + __ldg(&w[5]) + __ldg(&w[8]) + __ldg(&w[11]));
#pragma unroll
    for (int bb = 0; bb < 9; bb++) {
        const float om = __ldg(&w[3*(12 - bb) + 2]);
        bBa += ((pt >> bb) & 1) ? 0.5f*om : -0.5f*om;
    }
    const int PM[10] = {511,510,508,504,496,480,448,384,256,0};
    float Pv = 0.f;
#pragma unroll
    for (int tt = 0; tt < 10; tt++) {
        const float ph = __ldg(&w[75 - 3*tt]);
        Pv += (__popc(PM[tt] & pt) & 1) ? 0.5f*ph : -0.5f*ph;
    }
    const float Sv = (__popc(pt) & 1) ? 0.5f*__ldg(&w[39]) : -0.5f*__ldg(&w[39]);
    float sB, cB; __sincosf(bBa, &sB, &cB);
    float sP, cP; __sincosf(Pv,  &sP, &cP);
    float sS, cS; __sincosf(Sv,  &sS, &cS);
    const float t1r = cB*cP - sB*sP, t1i = cB*sP + sB*cP;
    const float t2r = cB*cP + sB*sP, t2i = sB*cP - cB*sP;
    const float w00r = t1r*cS - t1i*sS, w00i = t1r*sS + t1i*cS;
    const float w01r = t1r*cS + t1i*sS, w01i = t1i*cS - t1r*sS;
    const float w10r = t2r*cS - t2i*sS, w10i = t2r*sS + t2i*cS;
    const float w11r = t2r*cS + t2i*sS, w11i = t2i*cS - t2r*sS;

    // XOR-linear swizzled address bases (one LOP3 per access in the loops)
    const int pA1 = phys(t << 4);                                   // A1 store
    const int pA2 = phys((warp << 9) | ((lane & 16) << 4) | (lane & 15)); // A2 ld / C' st
    const int pCp = phys(pt);                                       // C' ld / L2 st
    const int pL2 = phys(((lane >> 1) << 9) | ((lane & 1) << 4) | warp); // L2 ld

    __syncthreads();   // BAR 1: tables visible (hidden under x-load latency)

    // ---- A0: layer-0 phi phase on the (unnormalized) real input ----
    const float4* tbl0f4 = reinterpret_cast<const float4*>(tbl0s);
#pragma unroll
    for (int kk = 0; kk < 8; kk++) {
        const float4 tb = tbl0f4[kk];
        {
            const int k0 = 2*kk;
            const float vr = cb0*tb.x - sb0*tb.y;
            const float vi = cb0*tb.y + sb0*tb.x;
            const float2 x0 = re[k0];
            re[k0] = f2mul(x0, make_float2(vr, vr));
            im[k0] = f2mul(x0, make_float2(vi, vi));
        }
        {
            const int k1 = 2*kk + 1;
            const float vr = cb0*tb.z - sb0*tb.w;
            const float vi = cb0*tb.w + sb0*tb.z;
            const float2 x1 = re[k1];
            re[k1] = f2mul(x1, make_float2(vr, vr));
            im[k1] = f2mul(x1, make_float2(vi, vi));
        }
    }

    // ==== LAYER 0 (tangent form) ====
    // pass A1: reg bits = i bits 0-3 (qubits 12..9)
    rotYt<0>(re, im, gt[12], gnt[12]);
    rotYt<1>(re, im, gt[11], gnt[11]);
    rotYt<2>(re, im, gt[10], gnt[10]);
    rotYt<3>(re, im, gt[ 9], gnt[ 9]);

    // warp-local exchange A1 -> A2 (reg bits = i bits 4-7)
#pragma unroll
    for (int k = 0; k < 16; k++)
        st[pA1 ^ phys(k)] = make_float4(re[k].x, re[k].y, im[k].x, im[k].y);
    __syncwarp();
#pragma unroll
    for (int k = 0; k < 16; k++) {
        const float4 v = st[pA2 ^ phys(k << 4)];
        re[k] = make_float2(v.x, v.y); im[k] = make_float2(v.z, v.w);
    }
    rotYt<0>(re, im, gt[8], gnt[8]);
    rotYt<1>(re, im, gt[7], gnt[7]);
    rotYt<2>(re, im, gt[6], gnt[6]);
    rotYt<3>(re, im, gt[5], gnt[5]);
    // shfl gate on i bit 8 (= lane bit 4), qubit 4
    {
        const float2 tSel = (lane & 16) ? gt[4] : gnt[4];
#pragma unroll
        for (int k = 0; k < 16; k++) {
            const u64 pr = __shfl_xor_sync(0xffffffffu, *(u64*)&re[k], 16);
            const u64 pi = __shfl_xor_sync(0xffffffffu, *(u64*)&im[k], 16);
            re[k] = f2fma(tSel, *(const float2*)&pr, re[k]);
            im[k] = f2fma(tSel, *(const float2*)&pi, im[k]);
        }
    }

    // block exchange A2 -> C' : i = (k<<9) | pt
#pragma unroll
    for (int k = 0; k < 16; k++)
        st[pA2 ^ phys(k << 4)] = make_float4(re[k].x, re[k].y, im[k].x, im[k].y);
    __syncthreads();                                             // BAR 2
#pragma unroll
    for (int k = 0; k < 16; k++) {
        const float4 v = st[pCp ^ phys(k << 9)];
        re[k] = make_float2(v.x, v.y); im[k] = make_float2(v.z, v.w);
    }
    // pass C': reg bits = i bits 9-12 (qubits 3..0)
    rotYt<0>(re, im, gt[3], gnt[3]);
    rotYt<1>(re, im, gt[2], gnt[2]);
    rotYt<2>(re, im, gt[1], gnt[1]);
    rotYt<3>(re, im, gt[0], gnt[0]);

    // ==== D01 diagonal: V[k] = W[s1(k)][s2(k)] * tbl1s[k] ====
    const float4* tbl1f4 = reinterpret_cast<const float4*>(tbl1s);
#pragma unroll
    for (int kk = 0; kk < 8; kk++) {
        const float4 tb = tbl1f4[kk];
#pragma unroll
        for (int h = 0; h < 2; h++) {
            const int k = 2*kk + h;
            const float tr_ = h ? tb.z : tb.x;
            const float ti_ = h ? tb.w : tb.y;
            const int s1 = __popc(k) & 1;
            const int s2 = __popc(k & 7) & 1;
            const float wr = s1 ? (s2 ? w11r : w10r) : (s2 ? w01r : w00r);
            const float wi = s1 ? (s2 ? w11i : w10i) : (s2 ? w01i : w00i);
            const float vr = wr*tr_ - wi*ti_;
            const float vi = wr*ti_ + wi*tr_;
            const float2 cd = make_float2(vr, vr);
            const float2 sd = make_float2(vi, vi);
            const float2 nd = make_float2(-vi, -vi);
            const float2 nr = f2fma(cd, re[k], f2mul(nd, im[k]));
            const float2 ni = f2fma(sd, re[k], f2mul(cd, im[k]));
            re[k] = nr; im[k] = ni;
        }
    }

    // ==== LAYER 1 (tangent form) ====
    // d12 = {11,12} (k-mask 12 in C'), orient = parity(i & 4095) : gate 13 (qubit 0)
    {
        const int Pt = __popc(pt) & 1;
#pragma unroll
        for (int k0 = 0; k0 < 8; k0++) {
            const int k1 = k0 ^ 12;
            const int o = Pt ^ (__popc(k0 & 7) & 1);
            const float2 ta_ = o ? gt[13] : gnt[13];
            const float2 tb_ = o ? gnt[13] : gt[13];
            const float2 ar = re[k0], ai = im[k0], br = re[k1], bi = im[k1];
            re[k0] = f2fma(ta_, br, ar);
            im[k0] = f2fma(ta_, bi, ai);
            re[k1] = f2fma(tb_, ar, br);
            im[k1] = f2fma(tb_, ai, bi);
        }
    }
    // d10 = {9,10} (k-mask 3 in C'), orient = parity(k & 14) : gate 15 (qubit 2)
    {
#pragma unroll
        for (int k0 = 0; k0 < 16; k0++) {
            if ((k0 & 3) > 1) continue;
            const int k1 = k0 ^ 3;
            const int o = __popc(k0 & 14) & 1;
            const float2 ta_ = o ? gt[15] : gnt[15];
            const float2 tb_ = o ? gnt[15] : gt[15];
            const float2 ar = re[k0], ai = im[k0], br = re[k1], bi = im[k1];
            re[k0] = f2fma(ta_, br, ar);
            im[k0] = f2fma(ta_, bi, ai);
            re[k1] = f2fma(tb_, ar, br);
            im[k1] = f2fma(tb_, ai, bi);
        }
    }

    // ==== warp-local exchange C' -> L2 (slots with i bits 0-3 = warp are
    // warp-private; store to the exact slots this warp read at C') ====
    // L2: reg k = i bits 5-8; lane bit0 = i4, lane bits 1-4 = i bits 9-12
#pragma unroll
    for (int k = 0; k < 16; k++)
        st[pCp ^ phys(k << 9)] = make_float4(re[k].x, re[k].y, im[k].x, im[k].y);
    __syncwarp();
#pragma unroll
    for (int k = 0; k < 16; k++) {
        const float4 v = st[pL2 ^ phys(k << 5)];
        re[k] = make_float2(v.x, v.y); im[k] = make_float2(v.z, v.w);
    }

    // d8 = {7,8} (k-mask 12 in L2), orient = i8 ^ parity(i9-12) : gate 17 (qubit 4)
    {
        const int oL = __popc(lane & 30) & 1;
        const float2 ta_ = oL ? gt[17] : gnt[17];
        const float2 tb_ = oL ? gnt[17] : gt[17];
#pragma unroll
        for (int k0 = 0; k0 < 8; k0++) {
            const int k1 = k0 ^ 12;
            const float2 ar = re[k0], ai = im[k0], br = re[k1], bi = im[k1];
            re[k0] = f2fma(ta_, br, ar);
            im[k0] = f2fma(ta_, bi, ai);
            re[k1] = f2fma(tb_, ar, br);
            im[k1] = f2fma(tb_, ai, bi);
        }
    }
    // d6 = {5,6} (k-mask 3 in L2), orient = parity(k&14) ^ parity(lane&30) : gate 19 (qubit 6)
    {
        const int oL = __popc(lane & 30) & 1;
#pragma unroll
        for (int k0 = 0; k0 < 16; k0++) {
            if ((k0 & 3) > 1) continue;
            const int k1 = k0 ^ 3;
            const int o = oL ^ (__popc(k0 & 14) & 1);
            const float2 ta_ = o ? gt[19] : gnt[19];
            const float2 tb_ = o ? gnt[19] : gt[19];
            const float2 ar = re[k0], ai = im[k0], br = re[k1], bi = im[k1];
            re[k0] = f2fma(ta_, br, ar);
            im[k0] = f2fma(ta_, bi, ai);
            re[k1] = f2fma(tb_, ar, br);
            im[k1] = f2fma(tb_, ai, bi);
        }
    }

    // ==== measurement: sign = parity(i & 4927) ====
    // L2: lane bits {0(i4),1(i9),4(i12)} -> 19; k bits {0(i5),3(i8)} -> 9; + popc(warp)
    const float2 mn1 = make_float2(-1.f, -1.f);
    const int sgt = (__popc(lane & 19) + __popc(warp)) & 1;
    float2 acc = make_float2(0.f, 0.f);
#pragma unroll
    for (int k = 0; k < 16; k++) {
        const float2 p = f2fma(re[k], re[k], f2mul(im[k], im[k]));
        if (__popc(k & 9) & 1) acc = f2fma(p, mn1, acc);
        else                   acc = f2add(acc, p);
    }
    if (sgt) acc = f2mul(acc, mn1);
#pragma unroll
    for (int o = 16; o > 0; o >>= 1) {
        u64 av = *(u64*)&acc;
        u64 ov = __shfl_xor_sync(0xffffffffu, av, o);
        acc = f2add(acc, *(float2*)&ov);
        u64 sv = *(u64*)&ss;
        u64 so = __shfl_xor_sync(0xffffffffu, sv, o);
        ss = f2add(ss, *(float2*)&so);
    }
    if (lane == 0) { red[warp] = acc; red2[warp] = ss; }
    __syncthreads();                                             // BAR 3
    if (t == 0) {
        float2 ta = make_float2(0.f, 0.f);
        float2 ts = make_float2(0.f, 0.f);
#pragma unroll
        for (int r = 0; r < 16; r++) { ta = f2add(ta, red[r]); ts = f2add(ts, red2[r]); }
        float C = 1.f;
#pragma unroll
        for (int g = 0; g < 13; g++) C *= gcs[g];
        C *= gcs[13] * gcs[15] * gcs[17] * gcs[19];
        const float C2 = C * C;
        out[2*b]   = C2 * ta.x / ts.x;
        out[2*b+1] = C2 * ta.y / ts.y;
    }
}

extern "C" void kernel_launch(void* const* d_in, const int* in_sizes, int n_in,
                              void* d_out, int out_size)
{
    const float* x = (const float*)d_in[0];
    const float* w = (const float*)d_in[1];
    float* out = (float*)d_out;
    const int B2 = (in_sizes[0] / DIM) / 2;        // 2 batch rows per CTA

    const size_t shmem = DIM * sizeof(float4);     // 128 KB
    cudaFuncSetAttribute(qc_kernel, cudaFuncAttributeMaxDynamicSharedMemorySize,
                         (int)shmem);
    qc_kernel<<<B2, 512, shmem>>>(x, w, out);      // single kernel
}